// round 9
// baseline (speedup 1.0000x reference)
#include <cuda_runtime.h>
#include <cuda_fp16.h>
#include <math.h>
#include <cstdint>

#define NTOK 32768
#define DM   2048
#define CORE 1024
#define MSLOT 256
#define NH   8
#define HD   128
#define INTER 4096
#define TOPK 4

// ---------------- scratch (device globals; no allocation) ----------------
__device__ __half g_kvh[NTOK * CORE];        // 64 MB
__device__ __half g_kvl[NTOK * CORE];        // 64 MB
__device__ float g_hid[MSLOT * INTER];
__device__ float g_qslots[MSLOT * CORE];
__device__ float g_att[NH * MSLOT * HD];
__device__ unsigned int g_idx[NH * NTOK];
__device__ int g_counts[NH * MSLOT];
__device__ float g_updin[MSLOT * 2 * CORE];
__device__ float g_h1[MSLOT * 2 * CORE];
__device__ float g_hu[MSLOT * 2 * CORE];
__device__ float g_h2[MSLOT * CORE];
__device__ float g_part[MSLOT * 16384];      // split-K partials (16 MB)
__device__ __half g_BhiT[CORE * DM];         // Wq^T hi
__device__ __half g_BloT[CORE * DM];         // Wq^T lo
__device__ __half g_W1h[INTER * CORE], g_W1l[INTER * CORE];
__device__ __half g_W2h[CORE * INTER], g_W2l[CORE * INTER];
__device__ __half g_U1h[2*CORE * 2*CORE], g_U1l[2*CORE * 2*CORE];
__device__ __half g_U2h[CORE * 2*CORE], g_U2l[CORE * 2*CORE];

// ================= warp-MMA helpers (sm_80+ PTX only) =================
__device__ __forceinline__ uint32_t smem_u32(const void* p) {
    uint32_t a;
    asm("{ .reg .u64 t; cvta.to.shared.u64 t, %1; cvt.u32.u64 %0, t; }" : "=r"(a) : "l"(p));
    return a;
}
__device__ __forceinline__ void ldsm_x4(uint32_t& r0, uint32_t& r1, uint32_t& r2, uint32_t& r3, uint32_t addr) {
    asm volatile("ldmatrix.sync.aligned.m8n8.x4.shared.b16 {%0,%1,%2,%3}, [%4];"
                 : "=r"(r0), "=r"(r1), "=r"(r2), "=r"(r3) : "r"(addr));
}
__device__ __forceinline__ void mma_fp16(float* d, const uint32_t* a, const uint32_t* b) {
    asm volatile("mma.sync.aligned.m16n8k16.row.col.f32.f16.f16.f32 "
                 "{%0,%1,%2,%3}, {%4,%5,%6,%7}, {%8,%9}, {%0,%1,%2,%3};"
                 : "+f"(d[0]), "+f"(d[1]), "+f"(d[2]), "+f"(d[3])
                 : "r"(a[0]), "r"(a[1]), "r"(a[2]), "r"(a[3]), "r"(b[0]), "r"(b[1]));
}
__device__ __forceinline__ uint32_t sw128(uint32_t off) { return off ^ ((off >> 3) & 0x70); }
__device__ __forceinline__ void cp_async16(uint32_t dst, const void* src) {
    asm volatile("cp.async.cg.shared.global [%0], [%1], 16;" :: "r"(dst), "l"(src) : "memory");
}
#define CP_COMMIT() asm volatile("cp.async.commit_group;" ::: "memory")
#define CP_WAIT(n)  asm volatile("cp.async.wait_group %0;" :: "n"(n) : "memory")

__device__ __forceinline__ uint32_t h2bits(__half2 h) { return *(uint32_t*)&h; }

// ================= generic W[K,N] -> W^T fp16 hi/lo split =================
__global__ void transB_gen(const float* __restrict__ W,
                           __half* __restrict__ BhiT,
                           __half* __restrict__ BloT, int K, int N)
{
    __shared__ float t[32][33];
    int n0 = blockIdx.x * 32, k0 = blockIdx.y * 32;
    int tx = threadIdx.x, ty = threadIdx.y;
#pragma unroll
    for (int i = 0; i < 4; i++)
        t[ty + i * 8][tx] = W[(size_t)(k0 + ty + i * 8) * N + n0 + tx];
    __syncthreads();
#pragma unroll
    for (int i = 0; i < 4; i++) {
        int n = n0 + ty + i * 8, k = k0 + tx;
        float v = t[tx][ty + i * 8];
        __half hi = __float2half_rn(v);
        float lo = v - __half2float(hi);
        BhiT[(size_t)n * K + k] = hi;
        BloT[(size_t)n * K + k] = __float2half_rn(lo);
    }
}

// ================= kv GEMM v4: direct-LDG A fragments + cp.async B =======
// A never touches smem: each thread LDGs its mma fragment fp32 pairs and
// converts to fp16 hi/lo in registers (one fp32 load feeds both terms).
// B (pre-split fp16) streams gmem->smem via cp.async, 4-stage ring.
#define KCH 32
#define OPTILE 16384
#define KV_NCH (DM / KCH)    // 64

__global__ __launch_bounds__(256) void kv_gemm_mma(
    const float* __restrict__ A,
    const __half* __restrict__ BhiT, const __half* __restrict__ BloT,
    const float* __restrict__ bias,
    __half* __restrict__ Ch, __half* __restrict__ Cl)
{
    extern __shared__ char smem[];
    const int tid = threadIdx.x;
    const int wid = tid >> 5, lane = tid & 31;
    const int wm = wid & 3, wn = wid >> 2;
    const int bm = blockIdx.y * 128;
    const int bn = blockIdx.x * 128;

    uint32_t sbase = smem_u32(smem);
    uint32_t s0 = (sbase + 1023u) & ~1023u;

    // B cp.async geometry: row = tid>>1, part=(tid&1): hi->bytes[0,64), lo->[64,128)
    const int brow = tid >> 1, bpart = tid & 1;
    const __half* bsrc = (bpart ? BloT : BhiT) + (size_t)(bn + brow) * DM;
    uint32_t bdoff[4];
#pragma unroll
    for (int e = 0; e < 4; e++) bdoff[e] = sw128(brow * 128 + bpart * 64 + e * 16);

    // direct A fragment geometry (canonical m16n8k16 A layout)
    const int fr = lane >> 2;            // fragment row 0..7
    const int fc = (lane & 3) * 2;       // fragment k pair 0,2,4,6
    const float* Arow = &A[(size_t)(bm + wm * 32 + fr) * DM + fc];

    // B ldsm geometry
    const int g = lane >> 3, r = lane & 7;
    const int b_n  = wn * 64 + ((g >> 1) & 1) * 8 + r;
    const int b_kb = (g & 1) * 16;

    float acc[2][8][4];
#pragma unroll
    for (int mb = 0; mb < 2; mb++)
#pragma unroll
        for (int nb = 0; nb < 8; nb++)
#pragma unroll
            for (int q = 0; q < 4; q++) acc[mb][nb][q] = 0.f;

    // prologue: issue B chunks 0..2
#pragma unroll
    for (int s = 0; s < 3; s++) {
        uint32_t base = s0 + s * OPTILE;
        const __half* bs_ = bsrc + s * KCH;
#pragma unroll
        for (int e = 0; e < 4; e++) cp_async16(base + bdoff[e], (const char*)bs_ + e * 16);
        CP_COMMIT();
    }

    for (int c = 0; c < KV_NCH; c++) {
        CP_WAIT(2);
        __syncthreads();

        if (c + 3 < KV_NCH) {
            uint32_t base = s0 + ((c + 3) & 3) * OPTILE;
            const __half* bs_ = bsrc + (c + 3) * KCH;
#pragma unroll
            for (int e = 0; e < 4; e++) cp_async16(base + bdoff[e], (const char*)bs_ + e * 16);
        }
        CP_COMMIT();   // commit every iter (possibly empty) to keep group count uniform

        const int kc = c * KCH;
        const uint32_t tBu = s0 + (c & 3) * OPTILE;
#pragma unroll
        for (int ks = 0; ks < 2; ks++) {
            // A fragments: direct LDG + convert (hi and lo from same fp32)
            uint32_t ah[2][4], al[2][4];
#pragma unroll
            for (int mb = 0; mb < 2; mb++) {
                const float* p0 = Arow + (size_t)(mb * 16) * DM + kc + ks * 16;
                float2 q00 = *(const float2*)(p0);
                float2 q10 = *(const float2*)(p0 + 8 * DM);
                float2 q01 = *(const float2*)(p0 + 8);
                float2 q11 = *(const float2*)(p0 + 8 * DM + 8);
                __half2 h00 = __floats2half2_rn(q00.x, q00.y);
                __half2 h10 = __floats2half2_rn(q10.x, q10.y);
                __half2 h01 = __floats2half2_rn(q01.x, q01.y);
                __half2 h11 = __floats2half2_rn(q11.x, q11.y);
                ah[mb][0] = h2bits(h00); ah[mb][1] = h2bits(h10);
                ah[mb][2] = h2bits(h01); ah[mb][3] = h2bits(h11);
                float2 f00 = __half22float2(h00);
                float2 f10 = __half22float2(h10);
                float2 f01 = __half22float2(h01);
                float2 f11 = __half22float2(h11);
                al[mb][0] = h2bits(__floats2half2_rn(q00.x - f00.x, q00.y - f00.y));
                al[mb][1] = h2bits(__floats2half2_rn(q10.x - f10.x, q10.y - f10.y));
                al[mb][2] = h2bits(__floats2half2_rn(q01.x - f01.x, q01.y - f01.y));
                al[mb][3] = h2bits(__floats2half2_rn(q11.x - f11.x, q11.y - f11.y));
            }
#pragma unroll
            for (int p = 0; p < 4; p++) {
                uint32_t bh[4], bl[4];
                uint32_t offH = sw128((b_n + p * 16) * 128 + ks * 32 + b_kb);
                uint32_t offL = sw128((b_n + p * 16) * 128 + 64 + ks * 32 + b_kb);
                ldsm_x4(bh[0], bh[1], bh[2], bh[3], tBu + offH);
                ldsm_x4(bl[0], bl[1], bl[2], bl[3], tBu + offL);
#pragma unroll
                for (int mb = 0; mb < 2; mb++) {
#pragma unroll
                    for (int half = 0; half < 2; half++) {
                        float* d = acc[mb][p * 2 + half];
                        mma_fp16(d, ah[mb], &bh[half * 2]);
                        mma_fp16(d, ah[mb], &bl[half * 2]);
                        mma_fp16(d, al[mb], &bh[half * 2]);
                    }
                }
            }
        }
        // no trailing sync needed: next iter's wait+sync orders buf reuse
    }

    // epilogue: add bias, split to fp16 hi/lo, store both
#pragma unroll
    for (int mb = 0; mb < 2; mb++) {
        int row0 = bm + wm * 32 + mb * 16 + (lane >> 2);
#pragma unroll
        for (int nb = 0; nb < 8; nb++) {
            int col = bn + wn * 64 + nb * 8 + (lane & 3) * 2;
            float2 b2 = *(const float2*)&bias[col];
            float v00 = acc[mb][nb][0] + b2.x, v01 = acc[mb][nb][1] + b2.y;
            float v10 = acc[mb][nb][2] + b2.x, v11 = acc[mb][nb][3] + b2.y;
            __half2 h0, l0, h1, l1;
            h0.x = __float2half_rn(v00); h0.y = __float2half_rn(v01);
            l0.x = __float2half_rn(v00 - __half2float(h0.x));
            l0.y = __float2half_rn(v01 - __half2float(h0.y));
            h1.x = __float2half_rn(v10); h1.y = __float2half_rn(v11);
            l1.x = __float2half_rn(v10 - __half2float(h1.x));
            l1.y = __float2half_rn(v11 - __half2float(h1.y));
            *(__half2*)&Ch[(size_t)row0 * CORE + col] = h0;
            *(__half2*)&Cl[(size_t)row0 * CORE + col] = l0;
            *(__half2*)&Ch[(size_t)(row0 + 8) * CORE + col] = h1;
            *(__half2*)&Cl[(size_t)(row0 + 8) * CORE + col] = l1;
        }
    }
}

// split-K HMMA fp16 GEMM (small M=256 GEMMs), 3-term.
__global__ __launch_bounds__(256) void gemm_sk_mma(
    const float* __restrict__ A,
    const __half* __restrict__ BhiT, const __half* __restrict__ BloT,
    float* __restrict__ Cpart, int Ktot, int Kslice, int N)
{
    extern __shared__ char smem[];
    const int tid = threadIdx.x;
    const int wid = tid >> 5, lane = tid & 31;
    const int wm = wid & 3, wn = wid >> 2;
    const int bm = blockIdx.y * 128;
    const int bn = blockIdx.x * 128;
    const int z  = blockIdx.z;
    const int k0 = z * Kslice;
    const int NCH = Kslice / KCH;

    uint32_t sbase = smem_u32(smem);
    uint32_t s0 = (sbase + 1023u) & ~1023u;
    char* smc = smem + (s0 - sbase);

    const int lrow  = tid >> 1;
    const int lhalf = tid & 1;
    const uint32_t stoff0  = sw128(lrow * 128 + lhalf * 32);
    const uint32_t stoff1  = sw128(lrow * 128 + lhalf * 32 + 16);
    const uint32_t stoff0L = sw128(lrow * 128 + 64 + lhalf * 32);
    const uint32_t stoff1L = sw128(lrow * 128 + 64 + lhalf * 32 + 16);

    const int g = lane >> 3, r = lane & 7;
    const int a_m  = wm * 32 + (g & 1) * 8 + r;
    const int a_kb = (g >> 1) * 16;
    const int b_n  = wn * 64 + ((g >> 1) & 1) * 8 + r;
    const int b_kb = (g & 1) * 16;

    float acc[2][8][4];
#pragma unroll
    for (int mb = 0; mb < 2; mb++)
#pragma unroll
        for (int nb = 0; nb < 8; nb++)
#pragma unroll
            for (int q = 0; q < 4; q++) acc[mb][nb][q] = 0.f;

    float4 av[4];
    float4 bhv[2], blv[2];
    {
        const float* ap = &A[(size_t)(bm + lrow) * Ktot + k0 + lhalf * 16];
#pragma unroll
        for (int j = 0; j < 4; j++) av[j] = *(const float4*)(ap + 4 * j);
        const __half* bhp = &BhiT[(size_t)(bn + lrow) * Ktot + k0 + lhalf * 16];
        const __half* blp = &BloT[(size_t)(bn + lrow) * Ktot + k0 + lhalf * 16];
        bhv[0] = *(const float4*)bhp; bhv[1] = *(const float4*)(bhp + 8);
        blv[0] = *(const float4*)blp; blv[1] = *(const float4*)(blp + 8);
    }

    for (int c = 0; c < NCH; c++) {
        const int buf = c & 1;
        char* tA = smc + buf * 2 * OPTILE;
        char* tB = tA + OPTILE;
        {
            __half2 h[8], l[8];
#pragma unroll
            for (int j = 0; j < 4; j++) {
                float f0 = av[j].x, f1 = av[j].y, f2 = av[j].z, f3 = av[j].w;
                __half h0 = __float2half_rn(f0), h1 = __float2half_rn(f1);
                __half h2 = __float2half_rn(f2), h3 = __float2half_rn(f3);
                h[2 * j].x = h0; h[2 * j].y = h1; h[2 * j + 1].x = h2; h[2 * j + 1].y = h3;
                l[2 * j].x = __float2half_rn(f0 - __half2float(h0));
                l[2 * j].y = __float2half_rn(f1 - __half2float(h1));
                l[2 * j + 1].x = __float2half_rn(f2 - __half2float(h2));
                l[2 * j + 1].y = __float2half_rn(f3 - __half2float(h3));
            }
            *(uint4*)(tA + stoff0)  = *(uint4*)&h[0];
            *(uint4*)(tA + stoff1)  = *(uint4*)&h[4];
            *(uint4*)(tA + stoff0L) = *(uint4*)&l[0];
            *(uint4*)(tA + stoff1L) = *(uint4*)&l[4];
            *(float4*)(tB + stoff0)  = bhv[0];
            *(float4*)(tB + stoff1)  = bhv[1];
            *(float4*)(tB + stoff0L) = blv[0];
            *(float4*)(tB + stoff1L) = blv[1];
        }
        __syncthreads();

        if (c + 1 < NCH) {
            const int kc = k0 + (c + 1) * KCH;
            const float* ap = &A[(size_t)(bm + lrow) * Ktot + kc + lhalf * 16];
#pragma unroll
            for (int j = 0; j < 4; j++) av[j] = *(const float4*)(ap + 4 * j);
            const __half* bhp = &BhiT[(size_t)(bn + lrow) * Ktot + kc + lhalf * 16];
            const __half* blp = &BloT[(size_t)(bn + lrow) * Ktot + kc + lhalf * 16];
            bhv[0] = *(const float4*)bhp; bhv[1] = *(const float4*)(bhp + 8);
            blv[0] = *(const float4*)blp; blv[1] = *(const float4*)(blp + 8);
        }

        const uint32_t tAu = s0 + buf * 2 * OPTILE;
        const uint32_t tBu = tAu + OPTILE;
#pragma unroll
        for (int ks = 0; ks < 2; ks++) {
            uint32_t ah[2][4], al[2][4];
#pragma unroll
            for (int mb = 0; mb < 2; mb++) {
                uint32_t offH = sw128((a_m + mb * 16) * 128 + ks * 32 + a_kb);
                uint32_t offL = sw128((a_m + mb * 16) * 128 + 64 + ks * 32 + a_kb);
                ldsm_x4(ah[mb][0], ah[mb][1], ah[mb][2], ah[mb][3], tAu + offH);
                ldsm_x4(al[mb][0], al[mb][1], al[mb][2], al[mb][3], tAu + offL);
            }
#pragma unroll
            for (int p = 0; p < 4; p++) {
                uint32_t bh[4], bl[4];
                uint32_t offH = sw128((b_n + p * 16) * 128 + ks * 32 + b_kb);
                uint32_t offL = sw128((b_n + p * 16) * 128 + 64 + ks * 32 + b_kb);
                ldsm_x4(bh[0], bh[1], bh[2], bh[3], tBu + offH);
                ldsm_x4(bl[0], bl[1], bl[2], bl[3], tBu + offL);
#pragma unroll
                for (int mb = 0; mb < 2; mb++) {
#pragma unroll
                    for (int half = 0; half < 2; half++) {
                        float* d = acc[mb][p * 2 + half];
                        mma_fp16(d, ah[mb], &bh[half * 2]);
                        mma_fp16(d, ah[mb], &bl[half * 2]);
                        mma_fp16(d, al[mb], &bh[half * 2]);
                    }
                }
            }
        }
        __syncthreads();
    }

    float* Cp = Cpart + (size_t)z * MSLOT * N;
#pragma unroll
    for (int mb = 0; mb < 2; mb++) {
        int row0 = bm + wm * 32 + mb * 16 + (lane >> 2);
#pragma unroll
        for (int nb = 0; nb < 8; nb++) {
            int col = bn + wn * 64 + nb * 8 + (lane & 3) * 2;
            *(float2*)&Cp[(size_t)row0 * N + col] = make_float2(acc[mb][nb][0], acc[mb][nb][1]);
            *(float2*)&Cp[(size_t)(row0 + 8) * N + col] = make_float2(acc[mb][nb][2], acc[mb][nb][3]);
        }
    }
}

// reduce split-K partials
template <bool RELU>
__global__ void reduce_sk(const float* __restrict__ Cpart, const float* __restrict__ bias,
                          float* __restrict__ C, int MN, int N, int SK)
{
    int i = blockIdx.x * 256 + threadIdx.x;
    if (i >= MN) return;
    float s = bias[i % N];
    for (int z = 0; z < SK; z++) s += Cpart[(size_t)z * MN + i];
    if (RELU) s = fmaxf(s, 0.f);
    C[i] = s;
}

// ================= scores GEMM: HMMA fp16 3-term =========================
__global__ __launch_bounds__(256) void scores_gemm_mma(
    const float* __restrict__ A,
    const __half* __restrict__ Bh, const __half* __restrict__ Bl,
    const float* __restrict__ mbias,
    float* __restrict__ out_scores, float* __restrict__ out_gate)
{
    extern __shared__ char smem[];
    const int tid = threadIdx.x;
    const int wid = tid >> 5, lane = tid & 31;
    const int wm = wid & 3, wn = wid >> 2;
    const int bm = blockIdx.y * 128;
    const int bn = blockIdx.x * 128;
    const int h  = blockIdx.z;
    const int k0 = h * HD;
    const int NCH = HD / KCH;   // 4

    uint32_t sbase = smem_u32(smem);
    uint32_t s0 = (sbase + 1023u) & ~1023u;
    char* smc = smem + (s0 - sbase);

    const int lrow  = tid >> 1;
    const int lhalf = tid & 1;
    const uint32_t stoff0  = sw128(lrow * 128 + lhalf * 32);
    const uint32_t stoff1  = sw128(lrow * 128 + lhalf * 32 + 16);
    const uint32_t stoff0L = sw128(lrow * 128 + 64 + lhalf * 32);
    const uint32_t stoff1L = sw128(lrow * 128 + 64 + lhalf * 32 + 16);

    const int g = lane >> 3, r = lane & 7;
    const int a_m  = wm * 32 + (g & 1) * 8 + r;
    const int a_kb = (g >> 1) * 16;
    const int b_n  = wn * 64 + ((g >> 1) & 1) * 8 + r;
    const int b_kb = (g & 1) * 16;

    float acc[2][8][4];
#pragma unroll
    for (int mb = 0; mb < 2; mb++)
#pragma unroll
        for (int nb = 0; nb < 8; nb++)
#pragma unroll
            for (int q = 0; q < 4; q++) acc[mb][nb][q] = 0.f;

    float4 av[4];
    float4 bhv[2], blv[2];
    {
        const float* ap = &A[(size_t)(bm + lrow) * CORE + k0 + lhalf * 16];
#pragma unroll
        for (int j = 0; j < 4; j++) av[j] = *(const float4*)(ap + 4 * j);
        const __half* bhp = &Bh[(size_t)(bn + lrow) * CORE + k0 + lhalf * 16];
        const __half* blp = &Bl[(size_t)(bn + lrow) * CORE + k0 + lhalf * 16];
        bhv[0] = *(const float4*)bhp; bhv[1] = *(const float4*)(bhp + 8);
        blv[0] = *(const float4*)blp; blv[1] = *(const float4*)(blp + 8);
    }

    for (int c = 0; c < NCH; c++) {
        const int buf = c & 1;
        char* tA = smc + buf * 2 * OPTILE;
        char* tB = tA + OPTILE;
        {
            __half2 hh[8], ll[8];
#pragma unroll
            for (int j = 0; j < 4; j++) {
                float f0 = av[j].x, f1 = av[j].y, f2 = av[j].z, f3 = av[j].w;
                __half h0 = __float2half_rn(f0), h1 = __float2half_rn(f1);
                __half h2 = __float2half_rn(f2), h3 = __float2half_rn(f3);
                hh[2 * j].x = h0; hh[2 * j].y = h1; hh[2 * j + 1].x = h2; hh[2 * j + 1].y = h3;
                ll[2 * j].x = __float2half_rn(f0 - __half2float(h0));
                ll[2 * j].y = __float2half_rn(f1 - __half2float(h1));
                ll[2 * j + 1].x = __float2half_rn(f2 - __half2float(h2));
                ll[2 * j + 1].y = __float2half_rn(f3 - __half2float(h3));
            }
            *(uint4*)(tA + stoff0)  = *(uint4*)&hh[0];
            *(uint4*)(tA + stoff1)  = *(uint4*)&hh[4];
            *(uint4*)(tA + stoff0L) = *(uint4*)&ll[0];
            *(uint4*)(tA + stoff1L) = *(uint4*)&ll[4];
            *(float4*)(tB + stoff0)  = bhv[0];
            *(float4*)(tB + stoff1)  = bhv[1];
            *(float4*)(tB + stoff0L) = blv[0];
            *(float4*)(tB + stoff1L) = blv[1];
        }
        __syncthreads();

        if (c + 1 < NCH) {
            const int kc = k0 + (c + 1) * KCH;
            const float* ap = &A[(size_t)(bm + lrow) * CORE + kc + lhalf * 16];
#pragma unroll
            for (int j = 0; j < 4; j++) av[j] = *(const float4*)(ap + 4 * j);
            const __half* bhp = &Bh[(size_t)(bn + lrow) * CORE + kc + lhalf * 16];
            const __half* blp = &Bl[(size_t)(bn + lrow) * CORE + kc + lhalf * 16];
            bhv[0] = *(const float4*)bhp; bhv[1] = *(const float4*)(bhp + 8);
            blv[0] = *(const float4*)blp; blv[1] = *(const float4*)(blp + 8);
        }

        const uint32_t tAu = s0 + buf * 2 * OPTILE;
        const uint32_t tBu = tAu + OPTILE;
#pragma unroll
        for (int ks = 0; ks < 2; ks++) {
            uint32_t ah[2][4], al[2][4];
#pragma unroll
            for (int mb = 0; mb < 2; mb++) {
                uint32_t offH = sw128((a_m + mb * 16) * 128 + ks * 32 + a_kb);
                uint32_t offL = sw128((a_m + mb * 16) * 128 + 64 + ks * 32 + a_kb);
                ldsm_x4(ah[mb][0], ah[mb][1], ah[mb][2], ah[mb][3], tAu + offH);
                ldsm_x4(al[mb][0], al[mb][1], al[mb][2], al[mb][3], tAu + offL);
            }
#pragma unroll
            for (int p = 0; p < 4; p++) {
                uint32_t bh[4], bl[4];
                uint32_t offH = sw128((b_n + p * 16) * 128 + ks * 32 + b_kb);
                uint32_t offL = sw128((b_n + p * 16) * 128 + 64 + ks * 32 + b_kb);
                ldsm_x4(bh[0], bh[1], bh[2], bh[3], tBu + offH);
                ldsm_x4(bl[0], bl[1], bl[2], bl[3], tBu + offL);
#pragma unroll
                for (int mb = 0; mb < 2; mb++) {
#pragma unroll
                    for (int half = 0; half < 2; half++) {
                        float* d = acc[mb][p * 2 + half];
                        mma_fp16(d, ah[mb], &bh[half * 2]);
                        mma_fp16(d, ah[mb], &bl[half * 2]);
                        mma_fp16(d, al[mb], &bh[half * 2]);
                    }
                }
            }
        }
        __syncthreads();
    }

    const float scale = 0.08838834764831845f;
#pragma unroll
    for (int mb = 0; mb < 2; mb++) {
        int m0 = bm + wm * 32 + mb * 16 + (lane >> 2);
        float bia0 = mbias[h * MSLOT + m0] * 5.0f;
        float bia1 = mbias[h * MSLOT + m0 + 8] * 5.0f;
        size_t base0 = ((size_t)(h * MSLOT + m0)) * NTOK + bn;
        size_t base1 = base0 + (size_t)8 * NTOK;
#pragma unroll
        for (int nb = 0; nb < 8; nb++) {
            int t = wn * 64 + nb * 8 + (lane & 3) * 2;
            float2 v0 = make_float2(acc[mb][nb][0] * scale + bia0, acc[mb][nb][1] * scale + bia0);
            float2 v1 = make_float2(acc[mb][nb][2] * scale + bia1, acc[mb][nb][3] * scale + bia1);
            *(float2*)&out_scores[base0 + t] = v0;
            *(float2*)&out_gate  [base0 + t] = v0;
            *(float2*)&out_scores[base1 + t] = v1;
            *(float2*)&out_gate  [base1 + t] = v1;
        }
    }
}

// ================= top-k over slots ===============
#define TCHUNK 64
__global__ __launch_bounds__(256) void topk_kernel(
    const float* __restrict__ scores,
    unsigned int* __restrict__ idx_out, int* __restrict__ counts)
{
    extern __shared__ float smemf[];
    float* sc_s = smemf;                 // [256][65]
    int*   hist = (int*)(sc_s + 256 * 65);

    const int h  = blockIdx.y;
    const int n0 = blockIdx.x * TCHUNK;
    const int tid = threadIdx.x;
    hist[tid] = 0;

    const int t = tid & 63, mo = tid >> 6;
    for (int rr = 0; rr < 64; rr++) {
        int m = rr * 4 + mo;
        sc_s[m * 65 + t] = scores[((size_t)(h * MSLOT + m)) * NTOK + n0 + t];
    }
    __syncthreads();

    const int warp = tid >> 5, lane = tid & 31;
    for (int tt = warp; tt < TCHUNK; tt += 8) {
        unsigned sel_pack = 0;
#pragma unroll
        for (int rr = 0; rr < TOPK; rr++) {
            float bv = -3.402823466e38f; int bi = 0;
#pragma unroll
            for (int j = 0; j < 8; j++) {
                int m = lane + j * 32;
                float v = sc_s[m * 65 + tt];
                if (v > bv) { bv = v; bi = m; }
            }
#pragma unroll
            for (int off = 16; off; off >>= 1) {
                float ov = __shfl_xor_sync(0xffffffffu, bv, off);
                int   oi = __shfl_xor_sync(0xffffffffu, bi, off);
                if (ov > bv || (ov == bv && oi < bi)) { bv = ov; bi = oi; }
            }
            if (lane == 0) sc_s[bi * 65 + tt] = -3.402823466e38f;
            __syncwarp();
            sel_pack |= ((unsigned)bi) << (8 * rr);
        }
        if (lane == 0) {
            idx_out[h * NTOK + n0 + tt] = sel_pack;
            atomicAdd(&hist[sel_pack & 255], 1);
            atomicAdd(&hist[(sel_pack >> 8) & 255], 1);
            atomicAdd(&hist[(sel_pack >> 16) & 255], 1);
            atomicAdd(&hist[(sel_pack >> 24) & 255], 1);
        }
    }
    __syncthreads();
    if (hist[tid]) atomicAdd(&counts[h * MSLOT + tid], hist[tid]);
}

// ---------------- attended accumulation (reads kvh+kvl) ----------------
__global__ __launch_bounds__(256) void attend_accum(
    const __half* __restrict__ kvh, const __half* __restrict__ kvl,
    const unsigned int* __restrict__ idx, float* __restrict__ att)
{
    extern __shared__ float a_s[];
    const int h  = blockIdx.y;
    const int n0 = blockIdx.x * 1024;
    const int tid = threadIdx.x;
    for (int i = tid; i < MSLOT * HD; i += 256) a_s[i] = 0.f;
    __syncthreads();

    const int warp = tid >> 5, lane = tid & 31;
    const int mlo = warp * 32, mhi = mlo + 32;

    for (int t = 0; t < 1024; t++) {
        unsigned p = idx[h * NTOK + n0 + t];
        const __half2* hrow = (const __half2*)&kvh[(size_t)(n0 + t) * CORE + h * HD];
        const __half2* lrow = (const __half2*)&kvl[(size_t)(n0 + t) * CORE + h * HD];
#pragma unroll
        for (int r = 0; r < TOPK; r++) {
            int m = (p >> (8 * r)) & 255;
            if (m >= mlo && m < mhi) {
                __half2 h0 = hrow[lane * 2],     h1 = hrow[lane * 2 + 1];
                __half2 l0 = lrow[lane * 2],     l1 = lrow[lane * 2 + 1];
                float4* dst = (float4*)&a_s[m * HD + lane * 4];
                float4 d = *dst;
                d.x += __half2float(h0.x) + __half2float(l0.x);
                d.y += __half2float(h0.y) + __half2float(l0.y);
                d.z += __half2float(h1.x) + __half2float(l1.x);
                d.w += __half2float(h1.y) + __half2float(l1.y);
                *dst = d;
            }
        }
    }
    __syncthreads();
    for (int i = tid; i < MSLOT * HD; i += 256) {
        float v = a_s[i];
        if (v != 0.f) atomicAdd(&att[(size_t)h * MSLOT * HD + i], v);
    }
}

// ---------------- build upd_in ----------------
__global__ void build_updin(const float* __restrict__ mem,
                            const float* __restrict__ att,
                            float* __restrict__ out)
{
    int row = blockIdx.x, tid = threadIdx.x;
    for (int i = tid; i < 2 * CORE; i += 256) {
        float v;
        if (i < CORE) v = mem[(size_t)row * CORE + i];
        else {
            int c = i - CORE; int h = c >> 7, d = c & 127;
            v = att[(h << 15) + row * HD + d];
        }
        out[(size_t)row * 2 * CORE + i] = v;
    }
}

// ---------------- layernorm ----------------
__global__ void ln_kernel(const float* __restrict__ x, const float* __restrict__ g,
                          const float* __restrict__ b, float* __restrict__ y, int L)
{
    int row = blockIdx.x, tid = threadIdx.x;
    const float* xr = &x[(size_t)row * L];
    float s = 0.f, s2 = 0.f;
    for (int i = tid; i < L; i += 256) { float v = xr[i]; s += v; s2 += v * v; }
    __shared__ float rs[8], rs2[8];
#pragma unroll
    for (int o = 16; o; o >>= 1) {
        s  += __shfl_xor_sync(0xffffffffu, s, o);
        s2 += __shfl_xor_sync(0xffffffffu, s2, o);
    }
    if ((tid & 31) == 0) { rs[tid >> 5] = s; rs2[tid >> 5] = s2; }
    __syncthreads();
    if (tid < 32) {
        s  = (tid < 8) ? rs[tid]  : 0.f;
        s2 = (tid < 8) ? rs2[tid] : 0.f;
#pragma unroll
        for (int o = 4; o; o >>= 1) {
            s  += __shfl_xor_sync(0xffffffffu, s, o);
            s2 += __shfl_xor_sync(0xffffffffu, s2, o);
        }
        if (tid == 0) { rs[0] = s; rs2[0] = s2; }
    }
    __syncthreads();
    float mu = rs[0] / (float)L;
    float var = rs2[0] / (float)L - mu * mu;
    float r = rsqrtf(var + 1e-5f);
    for (int i = tid; i < L; i += 256)
        y[(size_t)row * L + i] = (xr[i] - mu) * r * g[i] + b[i];
}

// ---------------- load fraction ----------------
__global__ void lf_kernel(const int* __restrict__ counts, float* __restrict__ out)
{
    int m = threadIdx.x;
    int s = 0;
#pragma unroll
    for (int h = 0; h < NH; h++) s += counts[h * MSLOT + m];
    out[m] = (float)s * 0.125f;
}

// ---------------- host launcher ----------------
extern "C" void kernel_launch(void* const* d_in, const int* in_sizes, int n_in,
                              void* d_out, int out_size)
{
    const float* bq_in   = (const float*)d_in[0];
    const float* mem     = (const float*)d_in[1];
    const float* Wq      = (const float*)d_in[2];
    const float* bq      = (const float*)d_in[3];
    const float* Ws1     = (const float*)d_in[4];
    const float* bs1     = (const float*)d_in[5];
    const float* Ws2     = (const float*)d_in[6];
    const float* bs2     = (const float*)d_in[7];
    const float* mbias   = (const float*)d_in[8];
    const float* ln1_g   = (const float*)d_in[9];
    const float* ln1_b   = (const float*)d_in[10];
    const float* Wu1     = (const float*)d_in[11];
    const float* bu1     = (const float*)d_in[12];
    const float* Wu2     = (const float*)d_in[13];
    const float* bu2     = (const float*)d_in[14];
    const float* lno_g   = (const float*)d_in[15];
    const float* lno_b   = (const float*)d_in[16];

    float* out = (float*)d_out;
    float* out_dyn    = out;
    float* out_scores = out + (size_t)MSLOT * CORE;
    float* out_gate   = out_scores + (size_t)NH * MSLOT * NTOK;
    float* out_lf     = out_gate + (size_t)NH * MSLOT * NTOK;

    void *p;
    cudaGetSymbolAddress(&p, g_kvh);     __half* kvh = (__half*)p;
    cudaGetSymbolAddress(&p, g_kvl);     __half* kvl = (__half*)p;
    cudaGetSymbolAddress(&p, g_hid);     float* hid = (float*)p;
    cudaGetSymbolAddress(&p, g_qslots);  float* qs  = (float*)p;
    cudaGetSymbolAddress(&p, g_att);     float* att = (float*)p;
    cudaGetSymbolAddress(&p, g_idx);     unsigned int* idxb = (unsigned int*)p;
    cudaGetSymbolAddress(&p, g_counts);  int* cnt = (int*)p;
    cudaGetSymbolAddress(&p, g_updin);   float* ui = (float*)p;
    cudaGetSymbolAddress(&p, g_h1);      float* h1 = (float*)p;
    cudaGetSymbolAddress(&p, g_hu);      float* hu = (float*)p;
    cudaGetSymbolAddress(&p, g_h2);      float* h2 = (float*)p;
    cudaGetSymbolAddress(&p, g_part);    float* part = (float*)p;
    cudaGetSymbolAddress(&p, g_BhiT);    __half* BhiT = (__half*)p;
    cudaGetSymbolAddress(&p, g_BloT);    __half* BloT = (__half*)p;
    cudaGetSymbolAddress(&p, g_W1h);     __half* W1h = (__half*)p;
    cudaGetSymbolAddress(&p, g_W1l);     __half* W1l = (__half*)p;
    cudaGetSymbolAddress(&p, g_W2h);     __half* W2h = (__half*)p;
    cudaGetSymbolAddress(&p, g_W2l);     __half* W2l = (__half*)p;
    cudaGetSymbolAddress(&p, g_U1h);     __half* U1h = (__half*)p;
    cudaGetSymbolAddress(&p, g_U1l);     __half* U1l = (__half*)p;
    cudaGetSymbolAddress(&p, g_U2h);     __half* U2h = (__half*)p;
    cudaGetSymbolAddress(&p, g_U2l);     __half* U2l = (__half*)p;

    int smkv = 4 * OPTILE + 1024;
    cudaFuncSetAttribute(kv_gemm_mma, cudaFuncAttributeMaxDynamicSharedMemorySize, smkv);
    int smg = 4 * OPTILE + 1024;
    cudaFuncSetAttribute(gemm_sk_mma, cudaFuncAttributeMaxDynamicSharedMemorySize, smg);
    cudaFuncSetAttribute(scores_gemm_mma, cudaFuncAttributeMaxDynamicSharedMemorySize, smg);
    int smt = 256 * 65 * 4 + 1024;
    cudaFuncSetAttribute(topk_kernel, cudaFuncAttributeMaxDynamicSharedMemorySize, smt);
    int sm3 = MSLOT * HD * 4;
    cudaFuncSetAttribute(attend_accum, cudaFuncAttributeMaxDynamicSharedMemorySize, sm3);

    // launches #1-#5, then kv_gemm at #6 (ncu -s 5 -c 1 capture target)
    cudaMemsetAsync(cnt, 0, NH * MSLOT * sizeof(int));                               // 1
    cudaMemsetAsync(att, 0, NH * MSLOT * HD * sizeof(float));                        // 2
    transB_gen<<<dim3(CORE / 32, DM / 32), dim3(32, 8)>>>(Wq, BhiT, BloT, DM, CORE); // 3
    transB_gen<<<dim3(INTER / 32, CORE / 32), dim3(32, 8)>>>(Ws1, W1h, W1l, CORE, INTER);  // 4
    transB_gen<<<dim3(CORE / 32, INTER / 32), dim3(32, 8)>>>(Ws2, W2h, W2l, INTER, CORE);  // 5

    // 6: kv = flat @ Wq + bq  -> kvh/kvl directly
    kv_gemm_mma<<<dim3(CORE / 128, NTOK / 128), 256, smkv>>>(bq_in, BhiT, BloT, bq, kvh, kvl);

    transB_gen<<<dim3(2 * CORE / 32, 2 * CORE / 32), dim3(32, 8)>>>(Wu1, U1h, U1l, 2 * CORE, 2 * CORE);
    transB_gen<<<dim3(CORE / 32, 2 * CORE / 32), dim3(32, 8)>>>(Wu2, U2h, U2l, 2 * CORE, CORE);

    // q_slots MLP (split-K HMMA fp16, 3-term)
    gemm_sk_mma<<<dim3(INTER / 128, 2, 4), 256, smg>>>(mem, W1h, W1l, part, CORE, 256, INTER);
    reduce_sk<true><<<(MSLOT * INTER + 255) / 256, 256>>>(part, bs1, hid, MSLOT * INTER, INTER, 4);
    gemm_sk_mma<<<dim3(CORE / 128, 2, 16), 256, smg>>>(hid, W2h, W2l, part, INTER, 256, CORE);
    reduce_sk<false><<<(MSLOT * CORE + 255) / 256, 256>>>(part, bs2, qs, MSLOT * CORE, CORE, 16);

    // scores GEMM + top-k
    scores_gemm_mma<<<dim3(NTOK / 128, MSLOT / 128, NH), 256, smg>>>(
        qs, kvh, kvl, mbias, out_scores, out_gate);
    topk_kernel<<<dim3(NTOK / TCHUNK, NH), 256, smt>>>(out_scores, idxb, cnt);

    // attended
    attend_accum<<<dim3(NTOK / 1024, NH), 256, sm3>>>(kvh, kvl, idxb, att);

    // update MLP
    build_updin<<<MSLOT, 256>>>(mem, att, ui);
    ln_kernel<<<MSLOT, 256>>>(ui, ln1_g, ln1_b, h1, 2 * CORE);
    gemm_sk_mma<<<dim3(2 * CORE / 128, 2, 8), 256, smg>>>(h1, U1h, U1l, part, 2 * CORE, 256, 2 * CORE);
    reduce_sk<true><<<(MSLOT * 2 * CORE + 255) / 256, 256>>>(part, bu1, hu, MSLOT * 2 * CORE, 2 * CORE, 8);
    gemm_sk_mma<<<dim3(CORE / 128, 2, 8), 256, smg>>>(hu, U2h, U2l, part, 2 * CORE, 256, CORE);
    reduce_sk<false><<<(MSLOT * CORE + 255) / 256, 256>>>(part, bu2, h2, MSLOT * CORE, CORE, 8);
    ln_kernel<<<MSLOT, 256>>>(h2, lno_g, lno_b, out_dyn, CORE);

    // load fraction
    lf_kernel<<<1, MSLOT>>>(cnt, out_lf);
}

// round 10
// speedup vs baseline: 1.1368x; 1.1368x over previous
#include <cuda_runtime.h>
#include <cuda_fp16.h>
#include <math.h>
#include <cstdint>

#define NTOK 32768
#define DM   2048
#define CORE 1024
#define MSLOT 256
#define NH   8
#define HD   128
#define INTER 4096
#define TOPK 4

// ---------------- scratch (device globals; no allocation) ----------------
__device__ __half g_kvh[NTOK * CORE];        // 64 MB
__device__ __half g_kvl[NTOK * CORE];        // 64 MB
__device__ float g_hid[MSLOT * INTER];
__device__ float g_qslots[MSLOT * CORE];
__device__ float g_att[NH * MSLOT * HD];
__device__ unsigned int g_idx[NH * NTOK];
__device__ int g_counts[NH * MSLOT];
__device__ float g_updin[MSLOT * 2 * CORE];
__device__ float g_h1[MSLOT * 2 * CORE];
__device__ float g_hu[MSLOT * 2 * CORE];
__device__ float g_h2[MSLOT * CORE];
__device__ float g_part[MSLOT * 16384];      // split-K partials (16 MB)
__device__ __half g_BhiT[CORE * DM];         // Wq^T hi
__device__ __half g_BloT[CORE * DM];         // Wq^T lo
__device__ __half g_W1h[INTER * CORE], g_W1l[INTER * CORE];
__device__ __half g_W2h[CORE * INTER], g_W2l[CORE * INTER];
__device__ __half g_U1h[2*CORE * 2*CORE], g_U1l[2*CORE * 2*CORE];
__device__ __half g_U2h[CORE * 2*CORE], g_U2l[CORE * 2*CORE];

// ================= warp-MMA helpers (sm_80+ PTX only) =================
__device__ __forceinline__ uint32_t smem_u32(const void* p) {
    uint32_t a;
    asm("{ .reg .u64 t; cvta.to.shared.u64 t, %1; cvt.u32.u64 %0, t; }" : "=r"(a) : "l"(p));
    return a;
}
__device__ __forceinline__ void ldsm_x4(uint32_t& r0, uint32_t& r1, uint32_t& r2, uint32_t& r3, uint32_t addr) {
    asm volatile("ldmatrix.sync.aligned.m8n8.x4.shared.b16 {%0,%1,%2,%3}, [%4];"
                 : "=r"(r0), "=r"(r1), "=r"(r2), "=r"(r3) : "r"(addr));
}
__device__ __forceinline__ void mma_fp16(float* d, const uint32_t* a, const uint32_t* b) {
    asm volatile("mma.sync.aligned.m16n8k16.row.col.f32.f16.f16.f32 "
                 "{%0,%1,%2,%3}, {%4,%5,%6,%7}, {%8,%9}, {%0,%1,%2,%3};"
                 : "+f"(d[0]), "+f"(d[1]), "+f"(d[2]), "+f"(d[3])
                 : "r"(a[0]), "r"(a[1]), "r"(a[2]), "r"(a[3]), "r"(b[0]), "r"(b[1]));
}
__device__ __forceinline__ uint32_t sw128(uint32_t off) { return off ^ ((off >> 3) & 0x70); }

// ================= generic W[K,N] -> W^T fp16 hi/lo split =================
__global__ void transB_gen(const float* __restrict__ W,
                           __half* __restrict__ BhiT,
                           __half* __restrict__ BloT, int K, int N)
{
    __shared__ float t[32][33];
    int n0 = blockIdx.x * 32, k0 = blockIdx.y * 32;
    int tx = threadIdx.x, ty = threadIdx.y;
#pragma unroll
    for (int i = 0; i < 4; i++)
        t[ty + i * 8][tx] = W[(size_t)(k0 + ty + i * 8) * N + n0 + tx];
    __syncthreads();
#pragma unroll
    for (int i = 0; i < 4; i++) {
        int n = n0 + ty + i * 8, k = k0 + tx;
        float v = t[tx][ty + i * 8];
        __half hi = __float2half_rn(v);
        float lo = v - __half2float(hi);
        BhiT[(size_t)n * K + k] = hi;
        BloT[(size_t)n * K + k] = __float2half_rn(lo);
    }
}

// ================= kv GEMM (R8-proven): register-staged, HMMA fp16 3-term =
#define KCH 32
#define OPTILE 16384

__global__ __launch_bounds__(256) void kv_gemm_mma(
    const float* __restrict__ A,
    const __half* __restrict__ BhiT, const __half* __restrict__ BloT,
    const float* __restrict__ bias,
    __half* __restrict__ Ch, __half* __restrict__ Cl)
{
    extern __shared__ char smem[];
    const int tid = threadIdx.x;
    const int wid = tid >> 5, lane = tid & 31;
    const int wm = wid & 3, wn = wid >> 2;
    const int bm = blockIdx.y * 128;
    const int bn = blockIdx.x * 128;
    const int NCH = DM / KCH;

    uint32_t sbase = smem_u32(smem);
    uint32_t s0 = (sbase + 1023u) & ~1023u;
    char* smc = smem + (s0 - sbase);

    const int lrow  = tid >> 1;
    const int lhalf = tid & 1;
    const uint32_t stoff0  = sw128(lrow * 128 + lhalf * 32);
    const uint32_t stoff1  = sw128(lrow * 128 + lhalf * 32 + 16);
    const uint32_t stoff0L = sw128(lrow * 128 + 64 + lhalf * 32);
    const uint32_t stoff1L = sw128(lrow * 128 + 64 + lhalf * 32 + 16);

    const int g = lane >> 3, r = lane & 7;
    const int a_m  = wm * 32 + (g & 1) * 8 + r;
    const int a_kb = (g >> 1) * 16;
    const int b_n  = wn * 64 + ((g >> 1) & 1) * 8 + r;
    const int b_kb = (g & 1) * 16;

    float acc[2][8][4];
#pragma unroll
    for (int mb = 0; mb < 2; mb++)
#pragma unroll
        for (int nb = 0; nb < 8; nb++)
#pragma unroll
            for (int q = 0; q < 4; q++) acc[mb][nb][q] = 0.f;

    float4 av[4];
    float4 bhv[2], blv[2];
    {
        const float* ap = &A[(size_t)(bm + lrow) * DM + lhalf * 16];
#pragma unroll
        for (int j = 0; j < 4; j++) av[j] = *(const float4*)(ap + 4 * j);
        const __half* bhp = &BhiT[(size_t)(bn + lrow) * DM + lhalf * 16];
        const __half* blp = &BloT[(size_t)(bn + lrow) * DM + lhalf * 16];
        bhv[0] = *(const float4*)bhp; bhv[1] = *(const float4*)(bhp + 8);
        blv[0] = *(const float4*)blp; blv[1] = *(const float4*)(blp + 8);
    }

    for (int c = 0; c < NCH; c++) {
        const int buf = c & 1;
        char* tA = smc + buf * 2 * OPTILE;
        char* tB = tA + OPTILE;
        {
            __half2 h[8], l[8];
#pragma unroll
            for (int j = 0; j < 4; j++) {
                float f0 = av[j].x, f1 = av[j].y, f2 = av[j].z, f3 = av[j].w;
                __half h0 = __float2half_rn(f0), h1 = __float2half_rn(f1);
                __half h2 = __float2half_rn(f2), h3 = __float2half_rn(f3);
                h[2 * j].x = h0; h[2 * j].y = h1; h[2 * j + 1].x = h2; h[2 * j + 1].y = h3;
                l[2 * j].x = __float2half_rn(f0 - __half2float(h0));
                l[2 * j].y = __float2half_rn(f1 - __half2float(h1));
                l[2 * j + 1].x = __float2half_rn(f2 - __half2float(h2));
                l[2 * j + 1].y = __float2half_rn(f3 - __half2float(h3));
            }
            *(uint4*)(tA + stoff0)  = *(uint4*)&h[0];
            *(uint4*)(tA + stoff1)  = *(uint4*)&h[4];
            *(uint4*)(tA + stoff0L) = *(uint4*)&l[0];
            *(uint4*)(tA + stoff1L) = *(uint4*)&l[4];
            *(float4*)(tB + stoff0)  = bhv[0];
            *(float4*)(tB + stoff1)  = bhv[1];
            *(float4*)(tB + stoff0L) = blv[0];
            *(float4*)(tB + stoff1L) = blv[1];
        }
        __syncthreads();

        if (c + 1 < NCH) {
            const int kc = (c + 1) * KCH;
            const float* ap = &A[(size_t)(bm + lrow) * DM + kc + lhalf * 16];
#pragma unroll
            for (int j = 0; j < 4; j++) av[j] = *(const float4*)(ap + 4 * j);
            const __half* bhp = &BhiT[(size_t)(bn + lrow) * DM + kc + lhalf * 16];
            const __half* blp = &BloT[(size_t)(bn + lrow) * DM + kc + lhalf * 16];
            bhv[0] = *(const float4*)bhp; bhv[1] = *(const float4*)(bhp + 8);
            blv[0] = *(const float4*)blp; blv[1] = *(const float4*)(blp + 8);
        }

        const uint32_t tAu = s0 + buf * 2 * OPTILE;
        const uint32_t tBu = tAu + OPTILE;
#pragma unroll
        for (int ks = 0; ks < 2; ks++) {
            uint32_t ah[2][4], al[2][4];
#pragma unroll
            for (int mb = 0; mb < 2; mb++) {
                uint32_t offH = sw128((a_m + mb * 16) * 128 + ks * 32 + a_kb);
                uint32_t offL = sw128((a_m + mb * 16) * 128 + 64 + ks * 32 + a_kb);
                ldsm_x4(ah[mb][0], ah[mb][1], ah[mb][2], ah[mb][3], tAu + offH);
                ldsm_x4(al[mb][0], al[mb][1], al[mb][2], al[mb][3], tAu + offL);
            }
#pragma unroll
            for (int p = 0; p < 4; p++) {
                uint32_t bh[4], bl[4];
                uint32_t offH = sw128((b_n + p * 16) * 128 + ks * 32 + b_kb);
                uint32_t offL = sw128((b_n + p * 16) * 128 + 64 + ks * 32 + b_kb);
                ldsm_x4(bh[0], bh[1], bh[2], bh[3], tBu + offH);
                ldsm_x4(bl[0], bl[1], bl[2], bl[3], tBu + offL);
#pragma unroll
                for (int mb = 0; mb < 2; mb++) {
#pragma unroll
                    for (int half = 0; half < 2; half++) {
                        float* d = acc[mb][p * 2 + half];
                        mma_fp16(d, ah[mb], &bh[half * 2]);
                        mma_fp16(d, ah[mb], &bl[half * 2]);
                        mma_fp16(d, al[mb], &bh[half * 2]);
                    }
                }
            }
        }
        __syncthreads();
    }

    // epilogue: add bias, split to fp16 hi/lo, store both
#pragma unroll
    for (int mb = 0; mb < 2; mb++) {
        int row0 = bm + wm * 32 + mb * 16 + (lane >> 2);
#pragma unroll
        for (int nb = 0; nb < 8; nb++) {
            int col = bn + wn * 64 + nb * 8 + (lane & 3) * 2;
            float2 b2 = *(const float2*)&bias[col];
            float v00 = acc[mb][nb][0] + b2.x, v01 = acc[mb][nb][1] + b2.y;
            float v10 = acc[mb][nb][2] + b2.x, v11 = acc[mb][nb][3] + b2.y;
            __half2 h0, l0, h1, l1;
            h0.x = __float2half_rn(v00); h0.y = __float2half_rn(v01);
            l0.x = __float2half_rn(v00 - __half2float(h0.x));
            l0.y = __float2half_rn(v01 - __half2float(h0.y));
            h1.x = __float2half_rn(v10); h1.y = __float2half_rn(v11);
            l1.x = __float2half_rn(v10 - __half2float(h1.x));
            l1.y = __float2half_rn(v11 - __half2float(h1.y));
            *(__half2*)&Ch[(size_t)row0 * CORE + col] = h0;
            *(__half2*)&Cl[(size_t)row0 * CORE + col] = l0;
            *(__half2*)&Ch[(size_t)(row0 + 8) * CORE + col] = h1;
            *(__half2*)&Cl[(size_t)(row0 + 8) * CORE + col] = l1;
        }
    }
}

// split-K HMMA fp16 GEMM (small M=256 GEMMs), 3-term.
__global__ __launch_bounds__(256) void gemm_sk_mma(
    const float* __restrict__ A,
    const __half* __restrict__ BhiT, const __half* __restrict__ BloT,
    float* __restrict__ Cpart, int Ktot, int Kslice, int N)
{
    extern __shared__ char smem[];
    const int tid = threadIdx.x;
    const int wid = tid >> 5, lane = tid & 31;
    const int wm = wid & 3, wn = wid >> 2;
    const int bm = blockIdx.y * 128;
    const int bn = blockIdx.x * 128;
    const int z  = blockIdx.z;
    const int k0 = z * Kslice;
    const int NCH = Kslice / KCH;

    uint32_t sbase = smem_u32(smem);
    uint32_t s0 = (sbase + 1023u) & ~1023u;
    char* smc = smem + (s0 - sbase);

    const int lrow  = tid >> 1;
    const int lhalf = tid & 1;
    const uint32_t stoff0  = sw128(lrow * 128 + lhalf * 32);
    const uint32_t stoff1  = sw128(lrow * 128 + lhalf * 32 + 16);
    const uint32_t stoff0L = sw128(lrow * 128 + 64 + lhalf * 32);
    const uint32_t stoff1L = sw128(lrow * 128 + 64 + lhalf * 32 + 16);

    const int g = lane >> 3, r = lane & 7;
    const int a_m  = wm * 32 + (g & 1) * 8 + r;
    const int a_kb = (g >> 1) * 16;
    const int b_n  = wn * 64 + ((g >> 1) & 1) * 8 + r;
    const int b_kb = (g & 1) * 16;

    float acc[2][8][4];
#pragma unroll
    for (int mb = 0; mb < 2; mb++)
#pragma unroll
        for (int nb = 0; nb < 8; nb++)
#pragma unroll
            for (int q = 0; q < 4; q++) acc[mb][nb][q] = 0.f;

    float4 av[4];
    float4 bhv[2], blv[2];
    {
        const float* ap = &A[(size_t)(bm + lrow) * Ktot + k0 + lhalf * 16];
#pragma unroll
        for (int j = 0; j < 4; j++) av[j] = *(const float4*)(ap + 4 * j);
        const __half* bhp = &BhiT[(size_t)(bn + lrow) * Ktot + k0 + lhalf * 16];
        const __half* blp = &BloT[(size_t)(bn + lrow) * Ktot + k0 + lhalf * 16];
        bhv[0] = *(const float4*)bhp; bhv[1] = *(const float4*)(bhp + 8);
        blv[0] = *(const float4*)blp; blv[1] = *(const float4*)(blp + 8);
    }

    for (int c = 0; c < NCH; c++) {
        const int buf = c & 1;
        char* tA = smc + buf * 2 * OPTILE;
        char* tB = tA + OPTILE;
        {
            __half2 h[8], l[8];
#pragma unroll
            for (int j = 0; j < 4; j++) {
                float f0 = av[j].x, f1 = av[j].y, f2 = av[j].z, f3 = av[j].w;
                __half h0 = __float2half_rn(f0), h1 = __float2half_rn(f1);
                __half h2 = __float2half_rn(f2), h3 = __float2half_rn(f3);
                h[2 * j].x = h0; h[2 * j].y = h1; h[2 * j + 1].x = h2; h[2 * j + 1].y = h3;
                l[2 * j].x = __float2half_rn(f0 - __half2float(h0));
                l[2 * j].y = __float2half_rn(f1 - __half2float(h1));
                l[2 * j + 1].x = __float2half_rn(f2 - __half2float(h2));
                l[2 * j + 1].y = __float2half_rn(f3 - __half2float(h3));
            }
            *(uint4*)(tA + stoff0)  = *(uint4*)&h[0];
            *(uint4*)(tA + stoff1)  = *(uint4*)&h[4];
            *(uint4*)(tA + stoff0L) = *(uint4*)&l[0];
            *(uint4*)(tA + stoff1L) = *(uint4*)&l[4];
            *(float4*)(tB + stoff0)  = bhv[0];
            *(float4*)(tB + stoff1)  = bhv[1];
            *(float4*)(tB + stoff0L) = blv[0];
            *(float4*)(tB + stoff1L) = blv[1];
        }
        __syncthreads();

        if (c + 1 < NCH) {
            const int kc = k0 + (c + 1) * KCH;
            const float* ap = &A[(size_t)(bm + lrow) * Ktot + kc + lhalf * 16];
#pragma unroll
            for (int j = 0; j < 4; j++) av[j] = *(const float4*)(ap + 4 * j);
            const __half* bhp = &BhiT[(size_t)(bn + lrow) * Ktot + kc + lhalf * 16];
            const __half* blp = &BloT[(size_t)(bn + lrow) * Ktot + kc + lhalf * 16];
            bhv[0] = *(const float4*)bhp; bhv[1] = *(const float4*)(bhp + 8);
            blv[0] = *(const float4*)blp; blv[1] = *(const float4*)(blp + 8);
        }

        const uint32_t tAu = s0 + buf * 2 * OPTILE;
        const uint32_t tBu = tAu + OPTILE;
#pragma unroll
        for (int ks = 0; ks < 2; ks++) {
            uint32_t ah[2][4], al[2][4];
#pragma unroll
            for (int mb = 0; mb < 2; mb++) {
                uint32_t offH = sw128((a_m + mb * 16) * 128 + ks * 32 + a_kb);
                uint32_t offL = sw128((a_m + mb * 16) * 128 + 64 + ks * 32 + a_kb);
                ldsm_x4(ah[mb][0], ah[mb][1], ah[mb][2], ah[mb][3], tAu + offH);
                ldsm_x4(al[mb][0], al[mb][1], al[mb][2], al[mb][3], tAu + offL);
            }
#pragma unroll
            for (int p = 0; p < 4; p++) {
                uint32_t bh[4], bl[4];
                uint32_t offH = sw128((b_n + p * 16) * 128 + ks * 32 + b_kb);
                uint32_t offL = sw128((b_n + p * 16) * 128 + 64 + ks * 32 + b_kb);
                ldsm_x4(bh[0], bh[1], bh[2], bh[3], tBu + offH);
                ldsm_x4(bl[0], bl[1], bl[2], bl[3], tBu + offL);
#pragma unroll
                for (int mb = 0; mb < 2; mb++) {
#pragma unroll
                    for (int half = 0; half < 2; half++) {
                        float* d = acc[mb][p * 2 + half];
                        mma_fp16(d, ah[mb], &bh[half * 2]);
                        mma_fp16(d, ah[mb], &bl[half * 2]);
                        mma_fp16(d, al[mb], &bh[half * 2]);
                    }
                }
            }
        }
        __syncthreads();
    }

    float* Cp = Cpart + (size_t)z * MSLOT * N;
#pragma unroll
    for (int mb = 0; mb < 2; mb++) {
        int row0 = bm + wm * 32 + mb * 16 + (lane >> 2);
#pragma unroll
        for (int nb = 0; nb < 8; nb++) {
            int col = bn + wn * 64 + nb * 8 + (lane & 3) * 2;
            *(float2*)&Cp[(size_t)row0 * N + col] = make_float2(acc[mb][nb][0], acc[mb][nb][1]);
            *(float2*)&Cp[(size_t)(row0 + 8) * N + col] = make_float2(acc[mb][nb][2], acc[mb][nb][3]);
        }
    }
}

// reduce split-K partials
template <bool RELU>
__global__ void reduce_sk(const float* __restrict__ Cpart, const float* __restrict__ bias,
                          float* __restrict__ C, int MN, int N, int SK)
{
    int i = blockIdx.x * 256 + threadIdx.x;
    if (i >= MN) return;
    float s = bias[i % N];
    for (int z = 0; z < SK; z++) s += Cpart[(size_t)z * MN + i];
    if (RELU) s = fmaxf(s, 0.f);
    C[i] = s;
}

// ================= scores GEMM + fused top-k ==============================
// One CTA = full 256-slot x 128-token tile for head h: two 128-row GEMM
// phases (acc reused), scores staged in smem [256][129] + written to gmem,
// then top-4 per token + histogram in-place. Bitwise-identical scores.
#define SCW 129
__global__ __launch_bounds__(256) void scores_topk_fused(
    const float* __restrict__ A,
    const __half* __restrict__ Bh, const __half* __restrict__ Bl,
    const float* __restrict__ mbias,
    float* __restrict__ out_scores, float* __restrict__ out_gate,
    unsigned int* __restrict__ idx_out, int* __restrict__ counts)
{
    extern __shared__ char smem[];
    const int tid = threadIdx.x;
    const int wid = tid >> 5, lane = tid & 31;
    const int wm = wid & 3, wn = wid >> 2;
    const int bn = blockIdx.x * 128;
    const int h  = blockIdx.y;
    const int k0 = h * HD;
    const int NCH = HD / KCH;   // 4

    uint32_t sbase = smem_u32(smem);
    uint32_t s0 = (sbase + 1023u) & ~1023u;
    char* smc = smem + (s0 - sbase);
    float* sc   = (float*)(smc + 4 * OPTILE);              // [256][129]
    int*   hist = (int*)(smc + 4 * OPTILE + MSLOT * SCW * 4);

    hist[tid] = 0;

    const int lrow  = tid >> 1;
    const int lhalf = tid & 1;
    const uint32_t stoff0  = sw128(lrow * 128 + lhalf * 32);
    const uint32_t stoff1  = sw128(lrow * 128 + lhalf * 32 + 16);
    const uint32_t stoff0L = sw128(lrow * 128 + 64 + lhalf * 32);
    const uint32_t stoff1L = sw128(lrow * 128 + 64 + lhalf * 32 + 16);

    const int g = lane >> 3, r = lane & 7;
    const int a_m  = wm * 32 + (g & 1) * 8 + r;
    const int a_kb = (g >> 1) * 16;
    const int b_n  = wn * 64 + ((g >> 1) & 1) * 8 + r;
    const int b_kb = (g & 1) * 16;

    const float scale = 0.08838834764831845f;

    for (int mh = 0; mh < 2; mh++) {
        const int bm = mh * 128;

        float acc[2][8][4];
#pragma unroll
        for (int mb = 0; mb < 2; mb++)
#pragma unroll
            for (int nb = 0; nb < 8; nb++)
#pragma unroll
                for (int q = 0; q < 4; q++) acc[mb][nb][q] = 0.f;

        float4 av[4];
        float4 bhv[2], blv[2];
        {
            const float* ap = &A[(size_t)(bm + lrow) * CORE + k0 + lhalf * 16];
#pragma unroll
            for (int j = 0; j < 4; j++) av[j] = *(const float4*)(ap + 4 * j);
            const __half* bhp = &Bh[(size_t)(bn + lrow) * CORE + k0 + lhalf * 16];
            const __half* blp = &Bl[(size_t)(bn + lrow) * CORE + k0 + lhalf * 16];
            bhv[0] = *(const float4*)bhp; bhv[1] = *(const float4*)(bhp + 8);
            blv[0] = *(const float4*)blp; blv[1] = *(const float4*)(blp + 8);
        }

        for (int c = 0; c < NCH; c++) {
            const int buf = c & 1;
            char* tA = smc + buf * 2 * OPTILE;
            char* tB = tA + OPTILE;
            {
                __half2 hh[8], ll[8];
#pragma unroll
                for (int j = 0; j < 4; j++) {
                    float f0 = av[j].x, f1 = av[j].y, f2 = av[j].z, f3 = av[j].w;
                    __half h0 = __float2half_rn(f0), h1 = __float2half_rn(f1);
                    __half h2 = __float2half_rn(f2), h3 = __float2half_rn(f3);
                    hh[2 * j].x = h0; hh[2 * j].y = h1; hh[2 * j + 1].x = h2; hh[2 * j + 1].y = h3;
                    ll[2 * j].x = __float2half_rn(f0 - __half2float(h0));
                    ll[2 * j].y = __float2half_rn(f1 - __half2float(h1));
                    ll[2 * j + 1].x = __float2half_rn(f2 - __half2float(h2));
                    ll[2 * j + 1].y = __float2half_rn(f3 - __half2float(h3));
                }
                *(uint4*)(tA + stoff0)  = *(uint4*)&hh[0];
                *(uint4*)(tA + stoff1)  = *(uint4*)&hh[4];
                *(uint4*)(tA + stoff0L) = *(uint4*)&ll[0];
                *(uint4*)(tA + stoff1L) = *(uint4*)&ll[4];
                *(float4*)(tB + stoff0)  = bhv[0];
                *(float4*)(tB + stoff1)  = bhv[1];
                *(float4*)(tB + stoff0L) = blv[0];
                *(float4*)(tB + stoff1L) = blv[1];
            }
            __syncthreads();

            if (c + 1 < NCH) {
                const int kc = k0 + (c + 1) * KCH;
                const float* ap = &A[(size_t)(bm + lrow) * CORE + kc + lhalf * 16];
#pragma unroll
                for (int j = 0; j < 4; j++) av[j] = *(const float4*)(ap + 4 * j);
                const __half* bhp = &Bh[(size_t)(bn + lrow) * CORE + kc + lhalf * 16];
                const __half* blp = &Bl[(size_t)(bn + lrow) * CORE + kc + lhalf * 16];
                bhv[0] = *(const float4*)bhp; bhv[1] = *(const float4*)(bhp + 8);
                blv[0] = *(const float4*)blp; blv[1] = *(const float4*)(blp + 8);
            }

            const uint32_t tAu = s0 + buf * 2 * OPTILE;
            const uint32_t tBu = tAu + OPTILE;
#pragma unroll
            for (int ks = 0; ks < 2; ks++) {
                uint32_t ah[2][4], al[2][4];
#pragma unroll
                for (int mb = 0; mb < 2; mb++) {
                    uint32_t offH = sw128((a_m + mb * 16) * 128 + ks * 32 + a_kb);
                    uint32_t offL = sw128((a_m + mb * 16) * 128 + 64 + ks * 32 + a_kb);
                    ldsm_x4(ah[mb][0], ah[mb][1], ah[mb][2], ah[mb][3], tAu + offH);
                    ldsm_x4(al[mb][0], al[mb][1], al[mb][2], al[mb][3], tAu + offL);
                }
#pragma unroll
                for (int p = 0; p < 4; p++) {
                    uint32_t bh[4], bl[4];
                    uint32_t offH = sw128((b_n + p * 16) * 128 + ks * 32 + b_kb);
                    uint32_t offL = sw128((b_n + p * 16) * 128 + 64 + ks * 32 + b_kb);
                    ldsm_x4(bh[0], bh[1], bh[2], bh[3], tBu + offH);
                    ldsm_x4(bl[0], bl[1], bl[2], bl[3], tBu + offL);
#pragma unroll
                    for (int mb = 0; mb < 2; mb++) {
#pragma unroll
                        for (int half = 0; half < 2; half++) {
                            float* d = acc[mb][p * 2 + half];
                            mma_fp16(d, ah[mb], &bh[half * 2]);
                            mma_fp16(d, ah[mb], &bl[half * 2]);
                            mma_fp16(d, al[mb], &bh[half * 2]);
                        }
                    }
                }
            }
            __syncthreads();
        }

        // epilogue: scale+bias, write gmem (both outputs) and smem sc
#pragma unroll
        for (int mb = 0; mb < 2; mb++) {
            int m0 = bm + wm * 32 + mb * 16 + (lane >> 2);
            float bia0 = mbias[h * MSLOT + m0] * 5.0f;
            float bia1 = mbias[h * MSLOT + m0 + 8] * 5.0f;
            size_t base0 = ((size_t)(h * MSLOT + m0)) * NTOK + bn;
            size_t base1 = base0 + (size_t)8 * NTOK;
#pragma unroll
            for (int nb = 0; nb < 8; nb++) {
                int t = wn * 64 + nb * 8 + (lane & 3) * 2;
                float2 v0 = make_float2(acc[mb][nb][0] * scale + bia0, acc[mb][nb][1] * scale + bia0);
                float2 v1 = make_float2(acc[mb][nb][2] * scale + bia1, acc[mb][nb][3] * scale + bia1);
                *(float2*)&out_scores[base0 + t] = v0;
                *(float2*)&out_gate  [base0 + t] = v0;
                *(float2*)&out_scores[base1 + t] = v1;
                *(float2*)&out_gate  [base1 + t] = v1;
                sc[m0 * SCW + t]       = v0.x;
                sc[m0 * SCW + t + 1]   = v0.y;
                sc[(m0 + 8) * SCW + t]     = v1.x;
                sc[(m0 + 8) * SCW + t + 1] = v1.y;
            }
        }
    }
    __syncthreads();

    // top-4 per token over all 256 slots (destructive, tie -> smaller index)
    const int warp = wid;
    for (int tt = warp; tt < 128; tt += 8) {
        unsigned sel_pack = 0;
#pragma unroll
        for (int rr = 0; rr < TOPK; rr++) {
            float bv = -3.402823466e38f; int bi = 0;
#pragma unroll
            for (int j = 0; j < 8; j++) {
                int m = lane + j * 32;
                float v = sc[m * SCW + tt];
                if (v > bv) { bv = v; bi = m; }
            }
#pragma unroll
            for (int off = 16; off; off >>= 1) {
                float ov = __shfl_xor_sync(0xffffffffu, bv, off);
                int   oi = __shfl_xor_sync(0xffffffffu, bi, off);
                if (ov > bv || (ov == bv && oi < bi)) { bv = ov; bi = oi; }
            }
            if (lane == 0) sc[bi * SCW + tt] = -3.402823466e38f;
            __syncwarp();
            sel_pack |= ((unsigned)bi) << (8 * rr);
        }
        if (lane == 0) {
            idx_out[h * NTOK + bn + tt] = sel_pack;
            atomicAdd(&hist[sel_pack & 255], 1);
            atomicAdd(&hist[(sel_pack >> 8) & 255], 1);
            atomicAdd(&hist[(sel_pack >> 16) & 255], 1);
            atomicAdd(&hist[(sel_pack >> 24) & 255], 1);
        }
    }
    __syncthreads();
    if (hist[tid]) atomicAdd(&counts[h * MSLOT + tid], hist[tid]);
}

// ---------------- attended accumulation (reads kvh+kvl) ----------------
__global__ __launch_bounds__(256) void attend_accum(
    const __half* __restrict__ kvh, const __half* __restrict__ kvl,
    const unsigned int* __restrict__ idx, float* __restrict__ att)
{
    extern __shared__ float a_s[];
    const int h  = blockIdx.y;
    const int n0 = blockIdx.x * 1024;
    const int tid = threadIdx.x;
    for (int i = tid; i < MSLOT * HD; i += 256) a_s[i] = 0.f;
    __syncthreads();

    const int warp = tid >> 5, lane = tid & 31;
    const int mlo = warp * 32, mhi = mlo + 32;

    for (int t = 0; t < 1024; t++) {
        unsigned p = idx[h * NTOK + n0 + t];
        const __half2* hrow = (const __half2*)&kvh[(size_t)(n0 + t) * CORE + h * HD];
        const __half2* lrow = (const __half2*)&kvl[(size_t)(n0 + t) * CORE + h * HD];
#pragma unroll
        for (int r = 0; r < TOPK; r++) {
            int m = (p >> (8 * r)) & 255;
            if (m >= mlo && m < mhi) {
                __half2 h0 = hrow[lane * 2],     h1 = hrow[lane * 2 + 1];
                __half2 l0 = lrow[lane * 2],     l1 = lrow[lane * 2 + 1];
                float4* dst = (float4*)&a_s[m * HD + lane * 4];
                float4 d = *dst;
                d.x += __half2float(h0.x) + __half2float(l0.x);
                d.y += __half2float(h0.y) + __half2float(l0.y);
                d.z += __half2float(h1.x) + __half2float(l1.x);
                d.w += __half2float(h1.y) + __half2float(l1.y);
                *dst = d;
            }
        }
    }
    __syncthreads();
    for (int i = tid; i < MSLOT * HD; i += 256) {
        float v = a_s[i];
        if (v != 0.f) atomicAdd(&att[(size_t)h * MSLOT * HD + i], v);
    }
}

// ---------------- build upd_in ----------------
__global__ void build_updin(const float* __restrict__ mem,
                            const float* __restrict__ att,
                            float* __restrict__ out)
{
    int row = blockIdx.x, tid = threadIdx.x;
    for (int i = tid; i < 2 * CORE; i += 256) {
        float v;
        if (i < CORE) v = mem[(size_t)row * CORE + i];
        else {
            int c = i - CORE; int h = c >> 7, d = c & 127;
            v = att[(h << 15) + row * HD + d];
        }
        out[(size_t)row * 2 * CORE + i] = v;
    }
}

// ---------------- layernorm ----------------
__global__ void ln_kernel(const float* __restrict__ x, const float* __restrict__ g,
                          const float* __restrict__ b, float* __restrict__ y, int L)
{
    int row = blockIdx.x, tid = threadIdx.x;
    const float* xr = &x[(size_t)row * L];
    float s = 0.f, s2 = 0.f;
    for (int i = tid; i < L; i += 256) { float v = xr[i]; s += v; s2 += v * v; }
    __shared__ float rs[8], rs2[8];
#pragma unroll
    for (int o = 16; o; o >>= 1) {
        s  += __shfl_xor_sync(0xffffffffu, s, o);
        s2 += __shfl_xor_sync(0xffffffffu, s2, o);
    }
    if ((tid & 31) == 0) { rs[tid >> 5] = s; rs2[tid >> 5] = s2; }
    __syncthreads();
    if (tid < 32) {
        s  = (tid < 8) ? rs[tid]  : 0.f;
        s2 = (tid < 8) ? rs2[tid] : 0.f;
#pragma unroll
        for (int o = 4; o; o >>= 1) {
            s  += __shfl_xor_sync(0xffffffffu, s, o);
            s2 += __shfl_xor_sync(0xffffffffu, s2, o);
        }
        if (tid == 0) { rs[0] = s; rs2[0] = s2; }
    }
    __syncthreads();
    float mu = rs[0] / (float)L;
    float var = rs2[0] / (float)L - mu * mu;
    float r = rsqrtf(var + 1e-5f);
    for (int i = tid; i < L; i += 256)
        y[(size_t)row * L + i] = (xr[i] - mu) * r * g[i] + b[i];
}

// ---------------- load fraction ----------------
__global__ void lf_kernel(const int* __restrict__ counts, float* __restrict__ out)
{
    int m = threadIdx.x;
    int s = 0;
#pragma unroll
    for (int h = 0; h < NH; h++) s += counts[h * MSLOT + m];
    out[m] = (float)s * 0.125f;
}

// ---------------- host launcher ----------------
extern "C" void kernel_launch(void* const* d_in, const int* in_sizes, int n_in,
                              void* d_out, int out_size)
{
    const float* bq_in   = (const float*)d_in[0];
    const float* mem     = (const float*)d_in[1];
    const float* Wq      = (const float*)d_in[2];
    const float* bq      = (const float*)d_in[3];
    const float* Ws1     = (const float*)d_in[4];
    const float* bs1     = (const float*)d_in[5];
    const float* Ws2     = (const float*)d_in[6];
    const float* bs2     = (const float*)d_in[7];
    const float* mbias   = (const float*)d_in[8];
    const float* ln1_g   = (const float*)d_in[9];
    const float* ln1_b   = (const float*)d_in[10];
    const float* Wu1     = (const float*)d_in[11];
    const float* bu1     = (const float*)d_in[12];
    const float* Wu2     = (const float*)d_in[13];
    const float* bu2     = (const float*)d_in[14];
    const float* lno_g   = (const float*)d_in[15];
    const float* lno_b   = (const float*)d_in[16];

    float* out = (float*)d_out;
    float* out_dyn    = out;
    float* out_scores = out + (size_t)MSLOT * CORE;
    float* out_gate   = out_scores + (size_t)NH * MSLOT * NTOK;
    float* out_lf     = out_gate + (size_t)NH * MSLOT * NTOK;

    void *p;
    cudaGetSymbolAddress(&p, g_kvh);     __half* kvh = (__half*)p;
    cudaGetSymbolAddress(&p, g_kvl);     __half* kvl = (__half*)p;
    cudaGetSymbolAddress(&p, g_hid);     float* hid = (float*)p;
    cudaGetSymbolAddress(&p, g_qslots);  float* qs  = (float*)p;
    cudaGetSymbolAddress(&p, g_att);     float* att = (float*)p;
    cudaGetSymbolAddress(&p, g_idx);     unsigned int* idxb = (unsigned int*)p;
    cudaGetSymbolAddress(&p, g_counts);  int* cnt = (int*)p;
    cudaGetSymbolAddress(&p, g_updin);   float* ui = (float*)p;
    cudaGetSymbolAddress(&p, g_h1);      float* h1 = (float*)p;
    cudaGetSymbolAddress(&p, g_hu);      float* hu = (float*)p;
    cudaGetSymbolAddress(&p, g_h2);      float* h2 = (float*)p;
    cudaGetSymbolAddress(&p, g_part);    float* part = (float*)p;
    cudaGetSymbolAddress(&p, g_BhiT);    __half* BhiT = (__half*)p;
    cudaGetSymbolAddress(&p, g_BloT);    __half* BloT = (__half*)p;
    cudaGetSymbolAddress(&p, g_W1h);     __half* W1h = (__half*)p;
    cudaGetSymbolAddress(&p, g_W1l);     __half* W1l = (__half*)p;
    cudaGetSymbolAddress(&p, g_W2h);     __half* W2h = (__half*)p;
    cudaGetSymbolAddress(&p, g_W2l);     __half* W2l = (__half*)p;
    cudaGetSymbolAddress(&p, g_U1h);     __half* U1h = (__half*)p;
    cudaGetSymbolAddress(&p, g_U1l);     __half* U1l = (__half*)p;
    cudaGetSymbolAddress(&p, g_U2h);     __half* U2h = (__half*)p;
    cudaGetSymbolAddress(&p, g_U2l);     __half* U2l = (__half*)p;

    int smg = 4 * OPTILE + 1024;
    cudaFuncSetAttribute(kv_gemm_mma, cudaFuncAttributeMaxDynamicSharedMemorySize, smg);
    cudaFuncSetAttribute(gemm_sk_mma, cudaFuncAttributeMaxDynamicSharedMemorySize, smg);
    int smf = 4 * OPTILE + MSLOT * SCW * 4 + 1024 + 1024;   // 64KB gemm + 129KB sc + hist + pad
    cudaFuncSetAttribute(scores_topk_fused, cudaFuncAttributeMaxDynamicSharedMemorySize, smf);
    int sm3 = MSLOT * HD * 4;
    cudaFuncSetAttribute(attend_accum, cudaFuncAttributeMaxDynamicSharedMemorySize, sm3);

    // launches #1-#5, then kv_gemm at #6 (ncu -s 5 -c 1 capture target)
    cudaMemsetAsync(cnt, 0, NH * MSLOT * sizeof(int));                               // 1
    cudaMemsetAsync(att, 0, NH * MSLOT * HD * sizeof(float));                        // 2
    transB_gen<<<dim3(CORE / 32, DM / 32), dim3(32, 8)>>>(Wq, BhiT, BloT, DM, CORE); // 3
    transB_gen<<<dim3(INTER / 32, CORE / 32), dim3(32, 8)>>>(Ws1, W1h, W1l, CORE, INTER);  // 4
    transB_gen<<<dim3(CORE / 32, INTER / 32), dim3(32, 8)>>>(Ws2, W2h, W2l, INTER, CORE);  // 5

    // 6: kv = flat @ Wq + bq  -> kvh/kvl directly
    kv_gemm_mma<<<dim3(CORE / 128, NTOK / 128), 256, smg>>>(bq_in, BhiT, BloT, bq, kvh, kvl);

    transB_gen<<<dim3(2 * CORE / 32, 2 * CORE / 32), dim3(32, 8)>>>(Wu1, U1h, U1l, 2 * CORE, 2 * CORE);
    transB_gen<<<dim3(CORE / 32, 2 * CORE / 32), dim3(32, 8)>>>(Wu2, U2h, U2l, 2 * CORE, CORE);

    // q_slots MLP (split-K HMMA fp16, 3-term)
    gemm_sk_mma<<<dim3(INTER / 128, 2, 4), 256, smg>>>(mem, W1h, W1l, part, CORE, 256, INTER);
    reduce_sk<true><<<(MSLOT * INTER + 255) / 256, 256>>>(part, bs1, hid, MSLOT * INTER, INTER, 4);
    gemm_sk_mma<<<dim3(CORE / 128, 2, 16), 256, smg>>>(hid, W2h, W2l, part, INTER, 256, CORE);
    reduce_sk<false><<<(MSLOT * CORE + 255) / 256, 256>>>(part, bs2, qs, MSLOT * CORE, CORE, 16);

    // scores GEMM + fused top-k
    scores_topk_fused<<<dim3(NTOK / 128, NH), 256, smf>>>(
        qs, kvh, kvl, mbias, out_scores, out_gate, idxb, cnt);

    // attended
    attend_accum<<<dim3(NTOK / 1024, NH), 256, sm3>>>(kvh, kvl, idxb, att);

    // update MLP
    build_updin<<<MSLOT, 256>>>(mem, att, ui);
    ln_kernel<<<MSLOT, 256>>>(ui, ln1_g, ln1_b, h1, 2 * CORE);
    gemm_sk_mma<<<dim3(2 * CORE / 128, 2, 8), 256, smg>>>(h1, U1h, U1l, part, 2 * CORE, 256, 2 * CORE);
    reduce_sk<true><<<(MSLOT * 2 * CORE + 255) / 256, 256>>>(part, bu1, hu, MSLOT * 2 * CORE, 2 * CORE, 8);
    gemm_sk_mma<<<dim3(CORE / 128, 2, 8), 256, smg>>>(hu, U2h, U2l, part, 2 * CORE, 256, CORE);
    reduce_sk<false><<<(MSLOT * CORE + 255) / 256, 256>>>(part, bu2, h2, MSLOT * CORE, CORE, 8);
    ln_kernel<<<MSLOT, 256>>>(h2, lno_g, lno_b, out_dyn, CORE);

    // load fraction
    lf_kernel<<<1, MSLOT>>>(cnt, out_lf);
}

// round 11
// speedup vs baseline: 1.1824x; 1.0401x over previous
#include <cuda_runtime.h>
#include <cuda_fp16.h>
#include <math.h>
#include <cstdint>

#define NTOK 32768
#define DM   2048
#define CORE 1024
#define MSLOT 256
#define NH   8
#define HD   128
#define INTER 4096
#define TOPK 4

// ---------------- scratch (device globals; no allocation) ----------------
__device__ __half g_kvh[NTOK * CORE];        // 64 MB
__device__ __half g_kvl[NTOK * CORE];        // 64 MB
__device__ float g_hid[MSLOT * INTER];
__device__ float g_qslots[MSLOT * CORE];
__device__ float g_att[NH * MSLOT * HD];
__device__ unsigned int g_idx[NH * NTOK];
__device__ int g_counts[NH * MSLOT];
__device__ float g_updin[MSLOT * 2 * CORE];
__device__ float g_h1[MSLOT * 2 * CORE];
__device__ float g_hu[MSLOT * 2 * CORE];
__device__ float g_h2[MSLOT * CORE];
__device__ float g_part[MSLOT * 16384];      // split-K partials (16 MB)
__device__ __half g_BhiT[CORE * DM];         // Wq^T hi
__device__ __half g_BloT[CORE * DM];         // Wq^T lo
__device__ __half g_W1h[INTER * CORE], g_W1l[INTER * CORE];
__device__ __half g_W2h[CORE * INTER], g_W2l[CORE * INTER];
__device__ __half g_U1h[2*CORE * 2*CORE], g_U1l[2*CORE * 2*CORE];
__device__ __half g_U2h[CORE * 2*CORE], g_U2l[CORE * 2*CORE];

// ================= warp-MMA helpers (sm_80+ PTX only) =================
__device__ __forceinline__ uint32_t smem_u32(const void* p) {
    uint32_t a;
    asm("{ .reg .u64 t; cvta.to.shared.u64 t, %1; cvt.u32.u64 %0, t; }" : "=r"(a) : "l"(p));
    return a;
}
__device__ __forceinline__ void ldsm_x4(uint32_t& r0, uint32_t& r1, uint32_t& r2, uint32_t& r3, uint32_t addr) {
    asm volatile("ldmatrix.sync.aligned.m8n8.x4.shared.b16 {%0,%1,%2,%3}, [%4];"
                 : "=r"(r0), "=r"(r1), "=r"(r2), "=r"(r3) : "r"(addr));
}
__device__ __forceinline__ void mma_fp16(float* d, const uint32_t* a, const uint32_t* b) {
    asm volatile("mma.sync.aligned.m16n8k16.row.col.f32.f16.f16.f32 "
                 "{%0,%1,%2,%3}, {%4,%5,%6,%7}, {%8,%9}, {%0,%1,%2,%3};"
                 : "+f"(d[0]), "+f"(d[1]), "+f"(d[2]), "+f"(d[3])
                 : "r"(a[0]), "r"(a[1]), "r"(a[2]), "r"(a[3]), "r"(b[0]), "r"(b[1]));
}
__device__ __forceinline__ uint32_t sw128(uint32_t off) { return off ^ ((off >> 3) & 0x70); }

// ================= generic W[K,N] -> W^T fp16 hi/lo split =================
__global__ void transB_gen(const float* __restrict__ W,
                           __half* __restrict__ BhiT,
                           __half* __restrict__ BloT, int K, int N)
{
    __shared__ float t[32][33];
    int n0 = blockIdx.x * 32, k0 = blockIdx.y * 32;
    int tx = threadIdx.x, ty = threadIdx.y;
#pragma unroll
    for (int i = 0; i < 4; i++)
        t[ty + i * 8][tx] = W[(size_t)(k0 + ty + i * 8) * N + n0 + tx];
    __syncthreads();
#pragma unroll
    for (int i = 0; i < 4; i++) {
        int n = n0 + ty + i * 8, k = k0 + tx;
        float v = t[tx][ty + i * 8];
        __half hi = __float2half_rn(v);
        float lo = v - __half2float(hi);
        BhiT[(size_t)n * K + k] = hi;
        BloT[(size_t)n * K + k] = __float2half_rn(lo);
    }
}

// ================= kv GEMM: register-staged, 3-buffer single-barrier =====
#define KCH 32
#define OPTILE 16384

__global__ __launch_bounds__(256) void kv_gemm_mma(
    const float* __restrict__ A,
    const __half* __restrict__ BhiT, const __half* __restrict__ BloT,
    const float* __restrict__ bias,
    __half* __restrict__ Ch, __half* __restrict__ Cl)
{
    extern __shared__ char smem[];
    const int tid = threadIdx.x;
    const int wid = tid >> 5, lane = tid & 31;
    const int wm = wid & 3, wn = wid >> 2;
    const int bm = blockIdx.y * 128;
    const int bn = blockIdx.x * 128;
    const int NCH = DM / KCH;

    uint32_t sbase = smem_u32(smem);
    uint32_t s0 = (sbase + 1023u) & ~1023u;
    char* smc = smem + (s0 - sbase);

    const int lrow  = tid >> 1;
    const int lhalf = tid & 1;
    const uint32_t stoff0  = sw128(lrow * 128 + lhalf * 32);
    const uint32_t stoff1  = sw128(lrow * 128 + lhalf * 32 + 16);
    const uint32_t stoff0L = sw128(lrow * 128 + 64 + lhalf * 32);
    const uint32_t stoff1L = sw128(lrow * 128 + 64 + lhalf * 32 + 16);

    const int g = lane >> 3, r = lane & 7;
    const int a_m  = wm * 32 + (g & 1) * 8 + r;
    const int a_kb = (g >> 1) * 16;
    const int b_n  = wn * 64 + ((g >> 1) & 1) * 8 + r;
    const int b_kb = (g & 1) * 16;

    float acc[2][8][4];
#pragma unroll
    for (int mb = 0; mb < 2; mb++)
#pragma unroll
        for (int nb = 0; nb < 8; nb++)
#pragma unroll
            for (int q = 0; q < 4; q++) acc[mb][nb][q] = 0.f;

    float4 av[4];
    float4 bhv[2], blv[2];
    {
        const float* ap = &A[(size_t)(bm + lrow) * DM + lhalf * 16];
#pragma unroll
        for (int j = 0; j < 4; j++) av[j] = *(const float4*)(ap + 4 * j);
        const __half* bhp = &BhiT[(size_t)(bn + lrow) * DM + lhalf * 16];
        const __half* blp = &BloT[(size_t)(bn + lrow) * DM + lhalf * 16];
        bhv[0] = *(const float4*)bhp; bhv[1] = *(const float4*)(bhp + 8);
        blv[0] = *(const float4*)blp; blv[1] = *(const float4*)(blp + 8);
    }

    // ring of 3 buffers; ONE barrier per chunk.
    // Safety: STS(c+1) [after sync(c)] cannot race MMA(c-2) [before sync(c-1)].
    int bufsel = 0;   // (c % 3)
    for (int c = 0; c < NCH; c++) {
        char* tA = smc + bufsel * 2 * OPTILE;
        char* tB = tA + OPTILE;
        {
            __half2 h[8], l[8];
#pragma unroll
            for (int j = 0; j < 4; j++) {
                float f0 = av[j].x, f1 = av[j].y, f2 = av[j].z, f3 = av[j].w;
                __half h0 = __float2half_rn(f0), h1 = __float2half_rn(f1);
                __half h2 = __float2half_rn(f2), h3 = __float2half_rn(f3);
                h[2 * j].x = h0; h[2 * j].y = h1; h[2 * j + 1].x = h2; h[2 * j + 1].y = h3;
                l[2 * j].x = __float2half_rn(f0 - __half2float(h0));
                l[2 * j].y = __float2half_rn(f1 - __half2float(h1));
                l[2 * j + 1].x = __float2half_rn(f2 - __half2float(h2));
                l[2 * j + 1].y = __float2half_rn(f3 - __half2float(h3));
            }
            *(uint4*)(tA + stoff0)  = *(uint4*)&h[0];
            *(uint4*)(tA + stoff1)  = *(uint4*)&h[4];
            *(uint4*)(tA + stoff0L) = *(uint4*)&l[0];
            *(uint4*)(tA + stoff1L) = *(uint4*)&l[4];
            *(float4*)(tB + stoff0)  = bhv[0];
            *(float4*)(tB + stoff1)  = bhv[1];
            *(float4*)(tB + stoff0L) = blv[0];
            *(float4*)(tB + stoff1L) = blv[1];
        }
        __syncthreads();

        if (c + 1 < NCH) {
            const int kc = (c + 1) * KCH;
            const float* ap = &A[(size_t)(bm + lrow) * DM + kc + lhalf * 16];
#pragma unroll
            for (int j = 0; j < 4; j++) av[j] = *(const float4*)(ap + 4 * j);
            const __half* bhp = &BhiT[(size_t)(bn + lrow) * DM + kc + lhalf * 16];
            const __half* blp = &BloT[(size_t)(bn + lrow) * DM + kc + lhalf * 16];
            bhv[0] = *(const float4*)bhp; bhv[1] = *(const float4*)(bhp + 8);
            blv[0] = *(const float4*)blp; blv[1] = *(const float4*)(blp + 8);
        }

        const uint32_t tAu = s0 + bufsel * 2 * OPTILE;
        const uint32_t tBu = tAu + OPTILE;
#pragma unroll
        for (int ks = 0; ks < 2; ks++) {
            uint32_t ah[2][4], al[2][4];
#pragma unroll
            for (int mb = 0; mb < 2; mb++) {
                uint32_t offH = sw128((a_m + mb * 16) * 128 + ks * 32 + a_kb);
                uint32_t offL = sw128((a_m + mb * 16) * 128 + 64 + ks * 32 + a_kb);
                ldsm_x4(ah[mb][0], ah[mb][1], ah[mb][2], ah[mb][3], tAu + offH);
                ldsm_x4(al[mb][0], al[mb][1], al[mb][2], al[mb][3], tAu + offL);
            }
#pragma unroll
            for (int p = 0; p < 4; p++) {
                uint32_t bh[4], bl[4];
                uint32_t offH = sw128((b_n + p * 16) * 128 + ks * 32 + b_kb);
                uint32_t offL = sw128((b_n + p * 16) * 128 + 64 + ks * 32 + b_kb);
                ldsm_x4(bh[0], bh[1], bh[2], bh[3], tBu + offH);
                ldsm_x4(bl[0], bl[1], bl[2], bl[3], tBu + offL);
#pragma unroll
                for (int mb = 0; mb < 2; mb++) {
#pragma unroll
                    for (int half = 0; half < 2; half++) {
                        float* d = acc[mb][p * 2 + half];
                        mma_fp16(d, ah[mb], &bh[half * 2]);
                        mma_fp16(d, ah[mb], &bl[half * 2]);
                        mma_fp16(d, al[mb], &bh[half * 2]);
                    }
                }
            }
        }
        bufsel++; if (bufsel == 3) bufsel = 0;
    }

    // epilogue: add bias, split to fp16 hi/lo, store both
#pragma unroll
    for (int mb = 0; mb < 2; mb++) {
        int row0 = bm + wm * 32 + mb * 16 + (lane >> 2);
#pragma unroll
        for (int nb = 0; nb < 8; nb++) {
            int col = bn + wn * 64 + nb * 8 + (lane & 3) * 2;
            float2 b2 = *(const float2*)&bias[col];
            float v00 = acc[mb][nb][0] + b2.x, v01 = acc[mb][nb][1] + b2.y;
            float v10 = acc[mb][nb][2] + b2.x, v11 = acc[mb][nb][3] + b2.y;
            __half2 h0, l0, h1, l1;
            h0.x = __float2half_rn(v00); h0.y = __float2half_rn(v01);
            l0.x = __float2half_rn(v00 - __half2float(h0.x));
            l0.y = __float2half_rn(v01 - __half2float(h0.y));
            h1.x = __float2half_rn(v10); h1.y = __float2half_rn(v11);
            l1.x = __float2half_rn(v10 - __half2float(h1.x));
            l1.y = __float2half_rn(v11 - __half2float(h1.y));
            *(__half2*)&Ch[(size_t)row0 * CORE + col] = h0;
            *(__half2*)&Cl[(size_t)row0 * CORE + col] = l0;
            *(__half2*)&Ch[(size_t)(row0 + 8) * CORE + col] = h1;
            *(__half2*)&Cl[(size_t)(row0 + 8) * CORE + col] = l1;
        }
    }
}

// split-K HMMA fp16 GEMM (small M=256 GEMMs), 3-term.
__global__ __launch_bounds__(256) void gemm_sk_mma(
    const float* __restrict__ A,
    const __half* __restrict__ BhiT, const __half* __restrict__ BloT,
    float* __restrict__ Cpart, int Ktot, int Kslice, int N)
{
    extern __shared__ char smem[];
    const int tid = threadIdx.x;
    const int wid = tid >> 5, lane = tid & 31;
    const int wm = wid & 3, wn = wid >> 2;
    const int bm = blockIdx.y * 128;
    const int bn = blockIdx.x * 128;
    const int z  = blockIdx.z;
    const int k0 = z * Kslice;
    const int NCH = Kslice / KCH;

    uint32_t sbase = smem_u32(smem);
    uint32_t s0 = (sbase + 1023u) & ~1023u;
    char* smc = smem + (s0 - sbase);

    const int lrow  = tid >> 1;
    const int lhalf = tid & 1;
    const uint32_t stoff0  = sw128(lrow * 128 + lhalf * 32);
    const uint32_t stoff1  = sw128(lrow * 128 + lhalf * 32 + 16);
    const uint32_t stoff0L = sw128(lrow * 128 + 64 + lhalf * 32);
    const uint32_t stoff1L = sw128(lrow * 128 + 64 + lhalf * 32 + 16);

    const int g = lane >> 3, r = lane & 7;
    const int a_m  = wm * 32 + (g & 1) * 8 + r;
    const int a_kb = (g >> 1) * 16;
    const int b_n  = wn * 64 + ((g >> 1) & 1) * 8 + r;
    const int b_kb = (g & 1) * 16;

    float acc[2][8][4];
#pragma unroll
    for (int mb = 0; mb < 2; mb++)
#pragma unroll
        for (int nb = 0; nb < 8; nb++)
#pragma unroll
            for (int q = 0; q < 4; q++) acc[mb][nb][q] = 0.f;

    float4 av[4];
    float4 bhv[2], blv[2];
    {
        const float* ap = &A[(size_t)(bm + lrow) * Ktot + k0 + lhalf * 16];
#pragma unroll
        for (int j = 0; j < 4; j++) av[j] = *(const float4*)(ap + 4 * j);
        const __half* bhp = &BhiT[(size_t)(bn + lrow) * Ktot + k0 + lhalf * 16];
        const __half* blp = &BloT[(size_t)(bn + lrow) * Ktot + k0 + lhalf * 16];
        bhv[0] = *(const float4*)bhp; bhv[1] = *(const float4*)(bhp + 8);
        blv[0] = *(const float4*)blp; blv[1] = *(const float4*)(blp + 8);
    }

    for (int c = 0; c < NCH; c++) {
        const int buf = c & 1;
        char* tA = smc + buf * 2 * OPTILE;
        char* tB = tA + OPTILE;
        {
            __half2 h[8], l[8];
#pragma unroll
            for (int j = 0; j < 4; j++) {
                float f0 = av[j].x, f1 = av[j].y, f2 = av[j].z, f3 = av[j].w;
                __half h0 = __float2half_rn(f0), h1 = __float2half_rn(f1);
                __half h2 = __float2half_rn(f2), h3 = __float2half_rn(f3);
                h[2 * j].x = h0; h[2 * j].y = h1; h[2 * j + 1].x = h2; h[2 * j + 1].y = h3;
                l[2 * j].x = __float2half_rn(f0 - __half2float(h0));
                l[2 * j].y = __float2half_rn(f1 - __half2float(h1));
                l[2 * j + 1].x = __float2half_rn(f2 - __half2float(h2));
                l[2 * j + 1].y = __float2half_rn(f3 - __half2float(h3));
            }
            *(uint4*)(tA + stoff0)  = *(uint4*)&h[0];
            *(uint4*)(tA + stoff1)  = *(uint4*)&h[4];
            *(uint4*)(tA + stoff0L) = *(uint4*)&l[0];
            *(uint4*)(tA + stoff1L) = *(uint4*)&l[4];
            *(float4*)(tB + stoff0)  = bhv[0];
            *(float4*)(tB + stoff1)  = bhv[1];
            *(float4*)(tB + stoff0L) = blv[0];
            *(float4*)(tB + stoff1L) = blv[1];
        }
        __syncthreads();

        if (c + 1 < NCH) {
            const int kc = k0 + (c + 1) * KCH;
            const float* ap = &A[(size_t)(bm + lrow) * Ktot + kc + lhalf * 16];
#pragma unroll
            for (int j = 0; j < 4; j++) av[j] = *(const float4*)(ap + 4 * j);
            const __half* bhp = &BhiT[(size_t)(bn + lrow) * Ktot + kc + lhalf * 16];
            const __half* blp = &BloT[(size_t)(bn + lrow) * Ktot + kc + lhalf * 16];
            bhv[0] = *(const float4*)bhp; bhv[1] = *(const float4*)(bhp + 8);
            blv[0] = *(const float4*)blp; blv[1] = *(const float4*)(blp + 8);
        }

        const uint32_t tAu = s0 + buf * 2 * OPTILE;
        const uint32_t tBu = tAu + OPTILE;
#pragma unroll
        for (int ks = 0; ks < 2; ks++) {
            uint32_t ah[2][4], al[2][4];
#pragma unroll
            for (int mb = 0; mb < 2; mb++) {
                uint32_t offH = sw128((a_m + mb * 16) * 128 + ks * 32 + a_kb);
                uint32_t offL = sw128((a_m + mb * 16) * 128 + 64 + ks * 32 + a_kb);
                ldsm_x4(ah[mb][0], ah[mb][1], ah[mb][2], ah[mb][3], tAu + offH);
                ldsm_x4(al[mb][0], al[mb][1], al[mb][2], al[mb][3], tAu + offL);
            }
#pragma unroll
            for (int p = 0; p < 4; p++) {
                uint32_t bh[4], bl[4];
                uint32_t offH = sw128((b_n + p * 16) * 128 + ks * 32 + b_kb);
                uint32_t offL = sw128((b_n + p * 16) * 128 + 64 + ks * 32 + b_kb);
                ldsm_x4(bh[0], bh[1], bh[2], bh[3], tBu + offH);
                ldsm_x4(bl[0], bl[1], bl[2], bl[3], tBu + offL);
#pragma unroll
                for (int mb = 0; mb < 2; mb++) {
#pragma unroll
                    for (int half = 0; half < 2; half++) {
                        float* d = acc[mb][p * 2 + half];
                        mma_fp16(d, ah[mb], &bh[half * 2]);
                        mma_fp16(d, ah[mb], &bl[half * 2]);
                        mma_fp16(d, al[mb], &bh[half * 2]);
                    }
                }
            }
        }
        __syncthreads();
    }

    float* Cp = Cpart + (size_t)z * MSLOT * N;
#pragma unroll
    for (int mb = 0; mb < 2; mb++) {
        int row0 = bm + wm * 32 + mb * 16 + (lane >> 2);
#pragma unroll
        for (int nb = 0; nb < 8; nb++) {
            int col = bn + wn * 64 + nb * 8 + (lane & 3) * 2;
            *(float2*)&Cp[(size_t)row0 * N + col] = make_float2(acc[mb][nb][0], acc[mb][nb][1]);
            *(float2*)&Cp[(size_t)(row0 + 8) * N + col] = make_float2(acc[mb][nb][2], acc[mb][nb][3]);
        }
    }
}

// reduce split-K partials
template <bool RELU>
__global__ void reduce_sk(const float* __restrict__ Cpart, const float* __restrict__ bias,
                          float* __restrict__ C, int MN, int N, int SK)
{
    int i = blockIdx.x * 256 + threadIdx.x;
    if (i >= MN) return;
    float s = bias[i % N];
    for (int z = 0; z < SK; z++) s += Cpart[(size_t)z * MN + i];
    if (RELU) s = fmaxf(s, 0.f);
    C[i] = s;
}

// ================= scores GEMM: HMMA fp16 3-term (R8-proven) =============
__global__ __launch_bounds__(256) void scores_gemm_mma(
    const float* __restrict__ A,
    const __half* __restrict__ Bh, const __half* __restrict__ Bl,
    const float* __restrict__ mbias,
    float* __restrict__ out_scores, float* __restrict__ out_gate)
{
    extern __shared__ char smem[];
    const int tid = threadIdx.x;
    const int wid = tid >> 5, lane = tid & 31;
    const int wm = wid & 3, wn = wid >> 2;
    const int bm = blockIdx.y * 128;
    const int bn = blockIdx.x * 128;
    const int h  = blockIdx.z;
    const int k0 = h * HD;
    const int NCH = HD / KCH;   // 4

    uint32_t sbase = smem_u32(smem);
    uint32_t s0 = (sbase + 1023u) & ~1023u;
    char* smc = smem + (s0 - sbase);

    const int lrow  = tid >> 1;
    const int lhalf = tid & 1;
    const uint32_t stoff0  = sw128(lrow * 128 + lhalf * 32);
    const uint32_t stoff1  = sw128(lrow * 128 + lhalf * 32 + 16);
    const uint32_t stoff0L = sw128(lrow * 128 + 64 + lhalf * 32);
    const uint32_t stoff1L = sw128(lrow * 128 + 64 + lhalf * 32 + 16);

    const int g = lane >> 3, r = lane & 7;
    const int a_m  = wm * 32 + (g & 1) * 8 + r;
    const int a_kb = (g >> 1) * 16;
    const int b_n  = wn * 64 + ((g >> 1) & 1) * 8 + r;
    const int b_kb = (g & 1) * 16;

    float acc[2][8][4];
#pragma unroll
    for (int mb = 0; mb < 2; mb++)
#pragma unroll
        for (int nb = 0; nb < 8; nb++)
#pragma unroll
            for (int q = 0; q < 4; q++) acc[mb][nb][q] = 0.f;

    float4 av[4];
    float4 bhv[2], blv[2];
    {
        const float* ap = &A[(size_t)(bm + lrow) * CORE + k0 + lhalf * 16];
#pragma unroll
        for (int j = 0; j < 4; j++) av[j] = *(const float4*)(ap + 4 * j);
        const __half* bhp = &Bh[(size_t)(bn + lrow) * CORE + k0 + lhalf * 16];
        const __half* blp = &Bl[(size_t)(bn + lrow) * CORE + k0 + lhalf * 16];
        bhv[0] = *(const float4*)bhp; bhv[1] = *(const float4*)(bhp + 8);
        blv[0] = *(const float4*)blp; blv[1] = *(const float4*)(blp + 8);
    }

    for (int c = 0; c < NCH; c++) {
        const int buf = c & 1;
        char* tA = smc + buf * 2 * OPTILE;
        char* tB = tA + OPTILE;
        {
            __half2 hh[8], ll[8];
#pragma unroll
            for (int j = 0; j < 4; j++) {
                float f0 = av[j].x, f1 = av[j].y, f2 = av[j].z, f3 = av[j].w;
                __half h0 = __float2half_rn(f0), h1 = __float2half_rn(f1);
                __half h2 = __float2half_rn(f2), h3 = __float2half_rn(f3);
                hh[2 * j].x = h0; hh[2 * j].y = h1; hh[2 * j + 1].x = h2; hh[2 * j + 1].y = h3;
                ll[2 * j].x = __float2half_rn(f0 - __half2float(h0));
                ll[2 * j].y = __float2half_rn(f1 - __half2float(h1));
                ll[2 * j + 1].x = __float2half_rn(f2 - __half2float(h2));
                ll[2 * j + 1].y = __float2half_rn(f3 - __half2float(h3));
            }
            *(uint4*)(tA + stoff0)  = *(uint4*)&hh[0];
            *(uint4*)(tA + stoff1)  = *(uint4*)&hh[4];
            *(uint4*)(tA + stoff0L) = *(uint4*)&ll[0];
            *(uint4*)(tA + stoff1L) = *(uint4*)&ll[4];
            *(float4*)(tB + stoff0)  = bhv[0];
            *(float4*)(tB + stoff1)  = bhv[1];
            *(float4*)(tB + stoff0L) = blv[0];
            *(float4*)(tB + stoff1L) = blv[1];
        }
        __syncthreads();

        if (c + 1 < NCH) {
            const int kc = k0 + (c + 1) * KCH;
            const float* ap = &A[(size_t)(bm + lrow) * CORE + kc + lhalf * 16];
#pragma unroll
            for (int j = 0; j < 4; j++) av[j] = *(const float4*)(ap + 4 * j);
            const __half* bhp = &Bh[(size_t)(bn + lrow) * CORE + kc + lhalf * 16];
            const __half* blp = &Bl[(size_t)(bn + lrow) * CORE + kc + lhalf * 16];
            bhv[0] = *(const float4*)bhp; bhv[1] = *(const float4*)(bhp + 8);
            blv[0] = *(const float4*)blp; blv[1] = *(const float4*)(blp + 8);
        }

        const uint32_t tAu = s0 + buf * 2 * OPTILE;
        const uint32_t tBu = tAu + OPTILE;
#pragma unroll
        for (int ks = 0; ks < 2; ks++) {
            uint32_t ah[2][4], al[2][4];
#pragma unroll
            for (int mb = 0; mb < 2; mb++) {
                uint32_t offH = sw128((a_m + mb * 16) * 128 + ks * 32 + a_kb);
                uint32_t offL = sw128((a_m + mb * 16) * 128 + 64 + ks * 32 + a_kb);
                ldsm_x4(ah[mb][0], ah[mb][1], ah[mb][2], ah[mb][3], tAu + offH);
                ldsm_x4(al[mb][0], al[mb][1], al[mb][2], al[mb][3], tAu + offL);
            }
#pragma unroll
            for (int p = 0; p < 4; p++) {
                uint32_t bh[4], bl[4];
                uint32_t offH = sw128((b_n + p * 16) * 128 + ks * 32 + b_kb);
                uint32_t offL = sw128((b_n + p * 16) * 128 + 64 + ks * 32 + b_kb);
                ldsm_x4(bh[0], bh[1], bh[2], bh[3], tBu + offH);
                ldsm_x4(bl[0], bl[1], bl[2], bl[3], tBu + offL);
#pragma unroll
                for (int mb = 0; mb < 2; mb++) {
#pragma unroll
                    for (int half = 0; half < 2; half++) {
                        float* d = acc[mb][p * 2 + half];
                        mma_fp16(d, ah[mb], &bh[half * 2]);
                        mma_fp16(d, ah[mb], &bl[half * 2]);
                        mma_fp16(d, al[mb], &bh[half * 2]);
                    }
                }
            }
        }
        __syncthreads();
    }

    const float scale = 0.08838834764831845f;
#pragma unroll
    for (int mb = 0; mb < 2; mb++) {
        int m0 = bm + wm * 32 + mb * 16 + (lane >> 2);
        float bia0 = mbias[h * MSLOT + m0] * 5.0f;
        float bia1 = mbias[h * MSLOT + m0 + 8] * 5.0f;
        size_t base0 = ((size_t)(h * MSLOT + m0)) * NTOK + bn;
        size_t base1 = base0 + (size_t)8 * NTOK;
#pragma unroll
        for (int nb = 0; nb < 8; nb++) {
            int t = wn * 64 + nb * 8 + (lane & 3) * 2;
            float2 v0 = make_float2(acc[mb][nb][0] * scale + bia0, acc[mb][nb][1] * scale + bia0);
            float2 v1 = make_float2(acc[mb][nb][2] * scale + bia1, acc[mb][nb][3] * scale + bia1);
            *(float2*)&out_scores[base0 + t] = v0;
            *(float2*)&out_gate  [base0 + t] = v0;
            *(float2*)&out_scores[base1 + t] = v1;
            *(float2*)&out_gate  [base1 + t] = v1;
        }
    }
}

// ================= top-k over slots (R8-proven) ===============
#define TCHUNK 64
__global__ __launch_bounds__(256) void topk_kernel(
    const float* __restrict__ scores,
    unsigned int* __restrict__ idx_out, int* __restrict__ counts)
{
    extern __shared__ float smemf[];
    float* sc_s = smemf;                 // [256][65]
    int*   hist = (int*)(sc_s + 256 * 65);

    const int h  = blockIdx.y;
    const int n0 = blockIdx.x * TCHUNK;
    const int tid = threadIdx.x;
    hist[tid] = 0;

    const int t = tid & 63, mo = tid >> 6;
    for (int rr = 0; rr < 64; rr++) {
        int m = rr * 4 + mo;
        sc_s[m * 65 + t] = scores[((size_t)(h * MSLOT + m)) * NTOK + n0 + t];
    }
    __syncthreads();

    const int warp = tid >> 5, lane = tid & 31;
    for (int tt = warp; tt < TCHUNK; tt += 8) {
        unsigned sel_pack = 0;
#pragma unroll
        for (int rr = 0; rr < TOPK; rr++) {
            float bv = -3.402823466e38f; int bi = 0;
#pragma unroll
            for (int j = 0; j < 8; j++) {
                int m = lane + j * 32;
                float v = sc_s[m * 65 + tt];
                if (v > bv) { bv = v; bi = m; }
            }
#pragma unroll
            for (int off = 16; off; off >>= 1) {
                float ov = __shfl_xor_sync(0xffffffffu, bv, off);
                int   oi = __shfl_xor_sync(0xffffffffu, bi, off);
                if (ov > bv || (ov == bv && oi < bi)) { bv = ov; bi = oi; }
            }
            if (lane == 0) sc_s[bi * 65 + tt] = -3.402823466e38f;
            __syncwarp();
            sel_pack |= ((unsigned)bi) << (8 * rr);
        }
        if (lane == 0) {
            idx_out[h * NTOK + n0 + tt] = sel_pack;
            atomicAdd(&hist[sel_pack & 255], 1);
            atomicAdd(&hist[(sel_pack >> 8) & 255], 1);
            atomicAdd(&hist[(sel_pack >> 16) & 255], 1);
            atomicAdd(&hist[(sel_pack >> 24) & 255], 1);
        }
    }
    __syncthreads();
    if (hist[tid]) atomicAdd(&counts[h * MSLOT + tid], hist[tid]);
}

// ---------------- attended accumulation (reads kvh+kvl) ----------------
__global__ __launch_bounds__(256) void attend_accum(
    const __half* __restrict__ kvh, const __half* __restrict__ kvl,
    const unsigned int* __restrict__ idx, float* __restrict__ att)
{
    extern __shared__ float a_s[];
    const int h  = blockIdx.y;
    const int n0 = blockIdx.x * 1024;
    const int tid = threadIdx.x;
    for (int i = tid; i < MSLOT * HD; i += 256) a_s[i] = 0.f;
    __syncthreads();

    const int warp = tid >> 5, lane = tid & 31;
    const int mlo = warp * 32, mhi = mlo + 32;

    for (int t = 0; t < 1024; t++) {
        unsigned p = idx[h * NTOK + n0 + t];
        const __half2* hrow = (const __half2*)&kvh[(size_t)(n0 + t) * CORE + h * HD];
        const __half2* lrow = (const __half2*)&kvl[(size_t)(n0 + t) * CORE + h * HD];
#pragma unroll
        for (int r = 0; r < TOPK; r++) {
            int m = (p >> (8 * r)) & 255;
            if (m >= mlo && m < mhi) {
                __half2 h0 = hrow[lane * 2],     h1 = hrow[lane * 2 + 1];
                __half2 l0 = lrow[lane * 2],     l1 = lrow[lane * 2 + 1];
                float4* dst = (float4*)&a_s[m * HD + lane * 4];
                float4 d = *dst;
                d.x += __half2float(h0.x) + __half2float(l0.x);
                d.y += __half2float(h0.y) + __half2float(l0.y);
                d.z += __half2float(h1.x) + __half2float(l1.x);
                d.w += __half2float(h1.y) + __half2float(l1.y);
                *dst = d;
            }
        }
    }
    __syncthreads();
    for (int i = tid; i < MSLOT * HD; i += 256) {
        float v = a_s[i];
        if (v != 0.f) atomicAdd(&att[(size_t)h * MSLOT * HD + i], v);
    }
}

// ---------------- build upd_in ----------------
__global__ void build_updin(const float* __restrict__ mem,
                            const float* __restrict__ att,
                            float* __restrict__ out)
{
    int row = blockIdx.x, tid = threadIdx.x;
    for (int i = tid; i < 2 * CORE; i += 256) {
        float v;
        if (i < CORE) v = mem[(size_t)row * CORE + i];
        else {
            int c = i - CORE; int h = c >> 7, d = c & 127;
            v = att[(h << 15) + row * HD + d];
        }
        out[(size_t)row * 2 * CORE + i] = v;
    }
}

// ---------------- layernorm ----------------
__global__ void ln_kernel(const float* __restrict__ x, const float* __restrict__ g,
                          const float* __restrict__ b, float* __restrict__ y, int L)
{
    int row = blockIdx.x, tid = threadIdx.x;
    const float* xr = &x[(size_t)row * L];
    float s = 0.f, s2 = 0.f;
    for (int i = tid; i < L; i += 256) { float v = xr[i]; s += v; s2 += v * v; }
    __shared__ float rs[8], rs2[8];
#pragma unroll
    for (int o = 16; o; o >>= 1) {
        s  += __shfl_xor_sync(0xffffffffu, s, o);
        s2 += __shfl_xor_sync(0xffffffffu, s2, o);
    }
    if ((tid & 31) == 0) { rs[tid >> 5] = s; rs2[tid >> 5] = s2; }
    __syncthreads();
    if (tid < 32) {
        s  = (tid < 8) ? rs[tid]  : 0.f;
        s2 = (tid < 8) ? rs2[tid] : 0.f;
#pragma unroll
        for (int o = 4; o; o >>= 1) {
            s  += __shfl_xor_sync(0xffffffffu, s, o);
            s2 += __shfl_xor_sync(0xffffffffu, s2, o);
        }
        if (tid == 0) { rs[0] = s; rs2[0] = s2; }
    }
    __syncthreads();
    float mu = rs[0] / (float)L;
    float var = rs2[0] / (float)L - mu * mu;
    float r = rsqrtf(var + 1e-5f);
    for (int i = tid; i < L; i += 256)
        y[(size_t)row * L + i] = (xr[i] - mu) * r * g[i] + b[i];
}

// ---------------- load fraction ----------------
__global__ void lf_kernel(const int* __restrict__ counts, float* __restrict__ out)
{
    int m = threadIdx.x;
    int s = 0;
#pragma unroll
    for (int h = 0; h < NH; h++) s += counts[h * MSLOT + m];
    out[m] = (float)s * 0.125f;
}

// ---------------- host launcher ----------------
extern "C" void kernel_launch(void* const* d_in, const int* in_sizes, int n_in,
                              void* d_out, int out_size)
{
    const float* bq_in   = (const float*)d_in[0];
    const float* mem     = (const float*)d_in[1];
    const float* Wq      = (const float*)d_in[2];
    const float* bq      = (const float*)d_in[3];
    const float* Ws1     = (const float*)d_in[4];
    const float* bs1     = (const float*)d_in[5];
    const float* Ws2     = (const float*)d_in[6];
    const float* bs2     = (const float*)d_in[7];
    const float* mbias   = (const float*)d_in[8];
    const float* ln1_g   = (const float*)d_in[9];
    const float* ln1_b   = (const float*)d_in[10];
    const float* Wu1     = (const float*)d_in[11];
    const float* bu1     = (const float*)d_in[12];
    const float* Wu2     = (const float*)d_in[13];
    const float* bu2     = (const float*)d_in[14];
    const float* lno_g   = (const float*)d_in[15];
    const float* lno_b   = (const float*)d_in[16];

    float* out = (float*)d_out;
    float* out_dyn    = out;
    float* out_scores = out + (size_t)MSLOT * CORE;
    float* out_gate   = out_scores + (size_t)NH * MSLOT * NTOK;
    float* out_lf     = out_gate + (size_t)NH * MSLOT * NTOK;

    void *p;
    cudaGetSymbolAddress(&p, g_kvh);     __half* kvh = (__half*)p;
    cudaGetSymbolAddress(&p, g_kvl);     __half* kvl = (__half*)p;
    cudaGetSymbolAddress(&p, g_hid);     float* hid = (float*)p;
    cudaGetSymbolAddress(&p, g_qslots);  float* qs  = (float*)p;
    cudaGetSymbolAddress(&p, g_att);     float* att = (float*)p;
    cudaGetSymbolAddress(&p, g_idx);     unsigned int* idxb = (unsigned int*)p;
    cudaGetSymbolAddress(&p, g_counts);  int* cnt = (int*)p;
    cudaGetSymbolAddress(&p, g_updin);   float* ui = (float*)p;
    cudaGetSymbolAddress(&p, g_h1);      float* h1 = (float*)p;
    cudaGetSymbolAddress(&p, g_hu);      float* hu = (float*)p;
    cudaGetSymbolAddress(&p, g_h2);      float* h2 = (float*)p;
    cudaGetSymbolAddress(&p, g_part);    float* part = (float*)p;
    cudaGetSymbolAddress(&p, g_BhiT);    __half* BhiT = (__half*)p;
    cudaGetSymbolAddress(&p, g_BloT);    __half* BloT = (__half*)p;
    cudaGetSymbolAddress(&p, g_W1h);     __half* W1h = (__half*)p;
    cudaGetSymbolAddress(&p, g_W1l);     __half* W1l = (__half*)p;
    cudaGetSymbolAddress(&p, g_W2h);     __half* W2h = (__half*)p;
    cudaGetSymbolAddress(&p, g_W2l);     __half* W2l = (__half*)p;
    cudaGetSymbolAddress(&p, g_U1h);     __half* U1h = (__half*)p;
    cudaGetSymbolAddress(&p, g_U1l);     __half* U1l = (__half*)p;
    cudaGetSymbolAddress(&p, g_U2h);     __half* U2h = (__half*)p;
    cudaGetSymbolAddress(&p, g_U2l);     __half* U2l = (__half*)p;

    int smkv = 6 * OPTILE + 1024;   // 3-buffer ring
    cudaFuncSetAttribute(kv_gemm_mma, cudaFuncAttributeMaxDynamicSharedMemorySize, smkv);
    int smg = 4 * OPTILE + 1024;
    cudaFuncSetAttribute(gemm_sk_mma, cudaFuncAttributeMaxDynamicSharedMemorySize, smg);
    cudaFuncSetAttribute(scores_gemm_mma, cudaFuncAttributeMaxDynamicSharedMemorySize, smg);
    int smt = 256 * 65 * 4 + 1024;
    cudaFuncSetAttribute(topk_kernel, cudaFuncAttributeMaxDynamicSharedMemorySize, smt);
    int sm3 = MSLOT * HD * 4;
    cudaFuncSetAttribute(attend_accum, cudaFuncAttributeMaxDynamicSharedMemorySize, sm3);

    // launches #1-#5, then kv_gemm at #6 (ncu -s 5 -c 1 capture target)
    cudaMemsetAsync(cnt, 0, NH * MSLOT * sizeof(int));                               // 1
    cudaMemsetAsync(att, 0, NH * MSLOT * HD * sizeof(float));                        // 2
    transB_gen<<<dim3(CORE / 32, DM / 32), dim3(32, 8)>>>(Wq, BhiT, BloT, DM, CORE); // 3
    transB_gen<<<dim3(INTER / 32, CORE / 32), dim3(32, 8)>>>(Ws1, W1h, W1l, CORE, INTER);  // 4
    transB_gen<<<dim3(CORE / 32, INTER / 32), dim3(32, 8)>>>(Ws2, W2h, W2l, INTER, CORE);  // 5

    // 6: kv = flat @ Wq + bq  -> kvh/kvl directly
    kv_gemm_mma<<<dim3(CORE / 128, NTOK / 128), 256, smkv>>>(bq_in, BhiT, BloT, bq, kvh, kvl);

    transB_gen<<<dim3(2 * CORE / 32, 2 * CORE / 32), dim3(32, 8)>>>(Wu1, U1h, U1l, 2 * CORE, 2 * CORE);
    transB_gen<<<dim3(CORE / 32, 2 * CORE / 32), dim3(32, 8)>>>(Wu2, U2h, U2l, 2 * CORE, CORE);

    // q_slots MLP (split-K HMMA fp16, 3-term)
    gemm_sk_mma<<<dim3(INTER / 128, 2, 4), 256, smg>>>(mem, W1h, W1l, part, CORE, 256, INTER);
    reduce_sk<true><<<(MSLOT * INTER + 255) / 256, 256>>>(part, bs1, hid, MSLOT * INTER, INTER, 4);
    gemm_sk_mma<<<dim3(CORE / 128, 2, 16), 256, smg>>>(hid, W2h, W2l, part, INTER, 256, CORE);
    reduce_sk<false><<<(MSLOT * CORE + 255) / 256, 256>>>(part, bs2, qs, MSLOT * CORE, CORE, 16);

    // scores GEMM + separate top-k (R8 configuration)
    scores_gemm_mma<<<dim3(NTOK / 128, MSLOT / 128, NH), 256, smg>>>(
        qs, kvh, kvl, mbias, out_scores, out_gate);
    topk_kernel<<<dim3(NTOK / TCHUNK, NH), 256, smt>>>(out_scores, idxb, cnt);

    // attended
    attend_accum<<<dim3(NTOK / 1024, NH), 256, sm3>>>(kvh, kvl, idxb, att);

    // update MLP
    build_updin<<<MSLOT, 256>>>(mem, att, ui);
    ln_kernel<<<MSLOT, 256>>>(ui, ln1_g, ln1_b, h1, 2 * CORE);
    gemm_sk_mma<<<dim3(2 * CORE / 128, 2, 8), 256, smg>>>(h1, U1h, U1l, part, 2 * CORE, 256, 2 * CORE);
    reduce_sk<true><<<(MSLOT * 2 * CORE + 255) / 256, 256>>>(part, bu1, hu, MSLOT * 2 * CORE, 2 * CORE, 8);
    gemm_sk_mma<<<dim3(CORE / 128, 2, 8), 256, smg>>>(hu, U2h, U2l, part, 2 * CORE, 256, CORE);
    reduce_sk<false><<<(MSLOT * CORE + 255) / 256, 256>>>(part, bu2, h2, MSLOT * CORE, CORE, 8);
    ln_kernel<<<MSLOT, 256>>>(h2, lno_g, lno_b, out_dyn, CORE);

    // load fraction
    lf_kernel<<<1, MSLOT>>>(cnt, out_lf);
}

// round 12
// speedup vs baseline: 1.2197x; 1.0315x over previous
#include <cuda_runtime.h>
#include <cuda_fp16.h>
#include <math.h>
#include <cstdint>

#define NTOK 32768
#define DM   2048
#define CORE 1024
#define MSLOT 256
#define NH   8
#define HD   128
#define INTER 4096
#define TOPK 4

// ---------------- scratch (device globals; no allocation) ----------------
__device__ __half g_kvh[NTOK * CORE];        // 64 MB
__device__ __half g_kvl[NTOK * CORE];        // 64 MB
__device__ float g_hid[MSLOT * INTER];
__device__ float g_qslots[MSLOT * CORE];
__device__ float g_att[NH * MSLOT * HD];
__device__ unsigned int g_idx[NH * NTOK];
__device__ int g_counts[NH * MSLOT];
__device__ float g_updin[MSLOT * 2 * CORE];
__device__ float g_h1[MSLOT * 2 * CORE];
__device__ float g_hu[MSLOT * 2 * CORE];
__device__ float g_h2[MSLOT * CORE];
__device__ float g_part[MSLOT * 16384];      // split-K partials (16 MB)
__device__ __half g_BhiT[CORE * DM];         // Wq^T hi
__device__ __half g_BloT[CORE * DM];         // Wq^T lo
__device__ __half g_W1h[INTER * CORE], g_W1l[INTER * CORE];
__device__ __half g_W2h[CORE * INTER], g_W2l[CORE * INTER];
__device__ __half g_U1h[2*CORE * 2*CORE], g_U1l[2*CORE * 2*CORE];
__device__ __half g_U2h[CORE * 2*CORE], g_U2l[CORE * 2*CORE];

// ================= warp-MMA helpers (sm_80+ PTX only) =================
__device__ __forceinline__ uint32_t smem_u32(const void* p) {
    uint32_t a;
    asm("{ .reg .u64 t; cvta.to.shared.u64 t, %1; cvt.u32.u64 %0, t; }" : "=r"(a) : "l"(p));
    return a;
}
__device__ __forceinline__ void ldsm_x4(uint32_t& r0, uint32_t& r1, uint32_t& r2, uint32_t& r3, uint32_t addr) {
    asm volatile("ldmatrix.sync.aligned.m8n8.x4.shared.b16 {%0,%1,%2,%3}, [%4];"
                 : "=r"(r0), "=r"(r1), "=r"(r2), "=r"(r3) : "r"(addr));
}
__device__ __forceinline__ void mma_fp16(float* d, const uint32_t* a, const uint32_t* b) {
    asm volatile("mma.sync.aligned.m16n8k16.row.col.f32.f16.f16.f32 "
                 "{%0,%1,%2,%3}, {%4,%5,%6,%7}, {%8,%9}, {%0,%1,%2,%3};"
                 : "+f"(d[0]), "+f"(d[1]), "+f"(d[2]), "+f"(d[3])
                 : "r"(a[0]), "r"(a[1]), "r"(a[2]), "r"(a[3]), "r"(b[0]), "r"(b[1]));
}
__device__ __forceinline__ uint32_t sw128(uint32_t off) { return off ^ ((off >> 3) & 0x70); }

// ================= generic W[K,N] -> W^T fp16 hi/lo split =================
__global__ void transB_gen(const float* __restrict__ W,
                           __half* __restrict__ BhiT,
                           __half* __restrict__ BloT, int K, int N)
{
    __shared__ float t[32][33];
    int n0 = blockIdx.x * 32, k0 = blockIdx.y * 32;
    int tx = threadIdx.x, ty = threadIdx.y;
#pragma unroll
    for (int i = 0; i < 4; i++)
        t[ty + i * 8][tx] = W[(size_t)(k0 + ty + i * 8) * N + n0 + tx];
    __syncthreads();
#pragma unroll
    for (int i = 0; i < 4; i++) {
        int n = n0 + ty + i * 8, k = k0 + tx;
        float v = t[tx][ty + i * 8];
        __half hi = __float2half_rn(v);
        float lo = v - __half2float(hi);
        BhiT[(size_t)n * K + k] = hi;
        BloT[(size_t)n * K + k] = __float2half_rn(lo);
    }
}

// ================= kv GEMM: register-staged, 3-buffer single-barrier =====
#define KCH 32
#define OPTILE 16384

__global__ __launch_bounds__(256) void kv_gemm_mma(
    const float* __restrict__ A,
    const __half* __restrict__ BhiT, const __half* __restrict__ BloT,
    const float* __restrict__ bias,
    __half* __restrict__ Ch, __half* __restrict__ Cl)
{
    extern __shared__ char smem[];
    const int tid = threadIdx.x;
    const int wid = tid >> 5, lane = tid & 31;
    const int wm = wid & 3, wn = wid >> 2;
    const int bm = blockIdx.y * 128;
    const int bn = blockIdx.x * 128;
    const int NCH = DM / KCH;

    uint32_t sbase = smem_u32(smem);
    uint32_t s0 = (sbase + 1023u) & ~1023u;
    char* smc = smem + (s0 - sbase);

    const int lrow  = tid >> 1;
    const int lhalf = tid & 1;
    const uint32_t stoff0  = sw128(lrow * 128 + lhalf * 32);
    const uint32_t stoff1  = sw128(lrow * 128 + lhalf * 32 + 16);
    const uint32_t stoff0L = sw128(lrow * 128 + 64 + lhalf * 32);
    const uint32_t stoff1L = sw128(lrow * 128 + 64 + lhalf * 32 + 16);

    const int g = lane >> 3, r = lane & 7;
    const int a_m  = wm * 32 + (g & 1) * 8 + r;
    const int a_kb = (g >> 1) * 16;
    const int b_n  = wn * 64 + ((g >> 1) & 1) * 8 + r;
    const int b_kb = (g & 1) * 16;

    float acc[2][8][4];
#pragma unroll
    for (int mb = 0; mb < 2; mb++)
#pragma unroll
        for (int nb = 0; nb < 8; nb++)
#pragma unroll
            for (int q = 0; q < 4; q++) acc[mb][nb][q] = 0.f;

    float4 av[4];
    float4 bhv[2], blv[2];
    {
        const float* ap = &A[(size_t)(bm + lrow) * DM + lhalf * 16];
#pragma unroll
        for (int j = 0; j < 4; j++) av[j] = *(const float4*)(ap + 4 * j);
        const __half* bhp = &BhiT[(size_t)(bn + lrow) * DM + lhalf * 16];
        const __half* blp = &BloT[(size_t)(bn + lrow) * DM + lhalf * 16];
        bhv[0] = *(const float4*)bhp; bhv[1] = *(const float4*)(bhp + 8);
        blv[0] = *(const float4*)blp; blv[1] = *(const float4*)(blp + 8);
    }

    int bufsel = 0;
    for (int c = 0; c < NCH; c++) {
        char* tA = smc + bufsel * 2 * OPTILE;
        char* tB = tA + OPTILE;
        {
            __half2 h[8], l[8];
#pragma unroll
            for (int j = 0; j < 4; j++) {
                float f0 = av[j].x, f1 = av[j].y, f2 = av[j].z, f3 = av[j].w;
                __half h0 = __float2half_rn(f0), h1 = __float2half_rn(f1);
                __half h2 = __float2half_rn(f2), h3 = __float2half_rn(f3);
                h[2 * j].x = h0; h[2 * j].y = h1; h[2 * j + 1].x = h2; h[2 * j + 1].y = h3;
                l[2 * j].x = __float2half_rn(f0 - __half2float(h0));
                l[2 * j].y = __float2half_rn(f1 - __half2float(h1));
                l[2 * j + 1].x = __float2half_rn(f2 - __half2float(h2));
                l[2 * j + 1].y = __float2half_rn(f3 - __half2float(h3));
            }
            *(uint4*)(tA + stoff0)  = *(uint4*)&h[0];
            *(uint4*)(tA + stoff1)  = *(uint4*)&h[4];
            *(uint4*)(tA + stoff0L) = *(uint4*)&l[0];
            *(uint4*)(tA + stoff1L) = *(uint4*)&l[4];
            *(float4*)(tB + stoff0)  = bhv[0];
            *(float4*)(tB + stoff1)  = bhv[1];
            *(float4*)(tB + stoff0L) = blv[0];
            *(float4*)(tB + stoff1L) = blv[1];
        }
        __syncthreads();

        if (c + 1 < NCH) {
            const int kc = (c + 1) * KCH;
            const float* ap = &A[(size_t)(bm + lrow) * DM + kc + lhalf * 16];
#pragma unroll
            for (int j = 0; j < 4; j++) av[j] = *(const float4*)(ap + 4 * j);
            const __half* bhp = &BhiT[(size_t)(bn + lrow) * DM + kc + lhalf * 16];
            const __half* blp = &BloT[(size_t)(bn + lrow) * DM + kc + lhalf * 16];
            bhv[0] = *(const float4*)bhp; bhv[1] = *(const float4*)(bhp + 8);
            blv[0] = *(const float4*)blp; blv[1] = *(const float4*)(blp + 8);
        }

        const uint32_t tAu = s0 + bufsel * 2 * OPTILE;
        const uint32_t tBu = tAu + OPTILE;
#pragma unroll
        for (int ks = 0; ks < 2; ks++) {
            uint32_t ah[2][4], al[2][4];
#pragma unroll
            for (int mb = 0; mb < 2; mb++) {
                uint32_t offH = sw128((a_m + mb * 16) * 128 + ks * 32 + a_kb);
                uint32_t offL = sw128((a_m + mb * 16) * 128 + 64 + ks * 32 + a_kb);
                ldsm_x4(ah[mb][0], ah[mb][1], ah[mb][2], ah[mb][3], tAu + offH);
                ldsm_x4(al[mb][0], al[mb][1], al[mb][2], al[mb][3], tAu + offL);
            }
#pragma unroll
            for (int p = 0; p < 4; p++) {
                uint32_t bh[4], bl[4];
                uint32_t offH = sw128((b_n + p * 16) * 128 + ks * 32 + b_kb);
                uint32_t offL = sw128((b_n + p * 16) * 128 + 64 + ks * 32 + b_kb);
                ldsm_x4(bh[0], bh[1], bh[2], bh[3], tBu + offH);
                ldsm_x4(bl[0], bl[1], bl[2], bl[3], tBu + offL);
#pragma unroll
                for (int mb = 0; mb < 2; mb++) {
#pragma unroll
                    for (int half = 0; half < 2; half++) {
                        float* d = acc[mb][p * 2 + half];
                        mma_fp16(d, ah[mb], &bh[half * 2]);
                        mma_fp16(d, ah[mb], &bl[half * 2]);
                        mma_fp16(d, al[mb], &bh[half * 2]);
                    }
                }
            }
        }
        bufsel++; if (bufsel == 3) bufsel = 0;
    }

#pragma unroll
    for (int mb = 0; mb < 2; mb++) {
        int row0 = bm + wm * 32 + mb * 16 + (lane >> 2);
#pragma unroll
        for (int nb = 0; nb < 8; nb++) {
            int col = bn + wn * 64 + nb * 8 + (lane & 3) * 2;
            float2 b2 = *(const float2*)&bias[col];
            float v00 = acc[mb][nb][0] + b2.x, v01 = acc[mb][nb][1] + b2.y;
            float v10 = acc[mb][nb][2] + b2.x, v11 = acc[mb][nb][3] + b2.y;
            __half2 h0, l0, h1, l1;
            h0.x = __float2half_rn(v00); h0.y = __float2half_rn(v01);
            l0.x = __float2half_rn(v00 - __half2float(h0.x));
            l0.y = __float2half_rn(v01 - __half2float(h0.y));
            h1.x = __float2half_rn(v10); h1.y = __float2half_rn(v11);
            l1.x = __float2half_rn(v10 - __half2float(h1.x));
            l1.y = __float2half_rn(v11 - __half2float(h1.y));
            *(__half2*)&Ch[(size_t)row0 * CORE + col] = h0;
            *(__half2*)&Cl[(size_t)row0 * CORE + col] = l0;
            *(__half2*)&Ch[(size_t)(row0 + 8) * CORE + col] = h1;
            *(__half2*)&Cl[(size_t)(row0 + 8) * CORE + col] = l1;
        }
    }
}

// split-K HMMA fp16 GEMM (small M=256 GEMMs), 3-term.
__global__ __launch_bounds__(256) void gemm_sk_mma(
    const float* __restrict__ A,
    const __half* __restrict__ BhiT, const __half* __restrict__ BloT,
    float* __restrict__ Cpart, int Ktot, int Kslice, int N)
{
    extern __shared__ char smem[];
    const int tid = threadIdx.x;
    const int wid = tid >> 5, lane = tid & 31;
    const int wm = wid & 3, wn = wid >> 2;
    const int bm = blockIdx.y * 128;
    const int bn = blockIdx.x * 128;
    const int z  = blockIdx.z;
    const int k0 = z * Kslice;
    const int NCH = Kslice / KCH;

    uint32_t sbase = smem_u32(smem);
    uint32_t s0 = (sbase + 1023u) & ~1023u;
    char* smc = smem + (s0 - sbase);

    const int lrow  = tid >> 1;
    const int lhalf = tid & 1;
    const uint32_t stoff0  = sw128(lrow * 128 + lhalf * 32);
    const uint32_t stoff1  = sw128(lrow * 128 + lhalf * 32 + 16);
    const uint32_t stoff0L = sw128(lrow * 128 + 64 + lhalf * 32);
    const uint32_t stoff1L = sw128(lrow * 128 + 64 + lhalf * 32 + 16);

    const int g = lane >> 3, r = lane & 7;
    const int a_m  = wm * 32 + (g & 1) * 8 + r;
    const int a_kb = (g >> 1) * 16;
    const int b_n  = wn * 64 + ((g >> 1) & 1) * 8 + r;
    const int b_kb = (g & 1) * 16;

    float acc[2][8][4];
#pragma unroll
    for (int mb = 0; mb < 2; mb++)
#pragma unroll
        for (int nb = 0; nb < 8; nb++)
#pragma unroll
            for (int q = 0; q < 4; q++) acc[mb][nb][q] = 0.f;

    float4 av[4];
    float4 bhv[2], blv[2];
    {
        const float* ap = &A[(size_t)(bm + lrow) * Ktot + k0 + lhalf * 16];
#pragma unroll
        for (int j = 0; j < 4; j++) av[j] = *(const float4*)(ap + 4 * j);
        const __half* bhp = &BhiT[(size_t)(bn + lrow) * Ktot + k0 + lhalf * 16];
        const __half* blp = &BloT[(size_t)(bn + lrow) * Ktot + k0 + lhalf * 16];
        bhv[0] = *(const float4*)bhp; bhv[1] = *(const float4*)(bhp + 8);
        blv[0] = *(const float4*)blp; blv[1] = *(const float4*)(blp + 8);
    }

    for (int c = 0; c < NCH; c++) {
        const int buf = c & 1;
        char* tA = smc + buf * 2 * OPTILE;
        char* tB = tA + OPTILE;
        {
            __half2 h[8], l[8];
#pragma unroll
            for (int j = 0; j < 4; j++) {
                float f0 = av[j].x, f1 = av[j].y, f2 = av[j].z, f3 = av[j].w;
                __half h0 = __float2half_rn(f0), h1 = __float2half_rn(f1);
                __half h2 = __float2half_rn(f2), h3 = __float2half_rn(f3);
                h[2 * j].x = h0; h[2 * j].y = h1; h[2 * j + 1].x = h2; h[2 * j + 1].y = h3;
                l[2 * j].x = __float2half_rn(f0 - __half2float(h0));
                l[2 * j].y = __float2half_rn(f1 - __half2float(h1));
                l[2 * j + 1].x = __float2half_rn(f2 - __half2float(h2));
                l[2 * j + 1].y = __float2half_rn(f3 - __half2float(h3));
            }
            *(uint4*)(tA + stoff0)  = *(uint4*)&h[0];
            *(uint4*)(tA + stoff1)  = *(uint4*)&h[4];
            *(uint4*)(tA + stoff0L) = *(uint4*)&l[0];
            *(uint4*)(tA + stoff1L) = *(uint4*)&l[4];
            *(float4*)(tB + stoff0)  = bhv[0];
            *(float4*)(tB + stoff1)  = bhv[1];
            *(float4*)(tB + stoff0L) = blv[0];
            *(float4*)(tB + stoff1L) = blv[1];
        }
        __syncthreads();

        if (c + 1 < NCH) {
            const int kc = k0 + (c + 1) * KCH;
            const float* ap = &A[(size_t)(bm + lrow) * Ktot + kc + lhalf * 16];
#pragma unroll
            for (int j = 0; j < 4; j++) av[j] = *(const float4*)(ap + 4 * j);
            const __half* bhp = &BhiT[(size_t)(bn + lrow) * Ktot + kc + lhalf * 16];
            const __half* blp = &BloT[(size_t)(bn + lrow) * Ktot + kc + lhalf * 16];
            bhv[0] = *(const float4*)bhp; bhv[1] = *(const float4*)(bhp + 8);
            blv[0] = *(const float4*)blp; blv[1] = *(const float4*)(blp + 8);
        }

        const uint32_t tAu = s0 + buf * 2 * OPTILE;
        const uint32_t tBu = tAu + OPTILE;
#pragma unroll
        for (int ks = 0; ks < 2; ks++) {
            uint32_t ah[2][4], al[2][4];
#pragma unroll
            for (int mb = 0; mb < 2; mb++) {
                uint32_t offH = sw128((a_m + mb * 16) * 128 + ks * 32 + a_kb);
                uint32_t offL = sw128((a_m + mb * 16) * 128 + 64 + ks * 32 + a_kb);
                ldsm_x4(ah[mb][0], ah[mb][1], ah[mb][2], ah[mb][3], tAu + offH);
                ldsm_x4(al[mb][0], al[mb][1], al[mb][2], al[mb][3], tAu + offL);
            }
#pragma unroll
            for (int p = 0; p < 4; p++) {
                uint32_t bh[4], bl[4];
                uint32_t offH = sw128((b_n + p * 16) * 128 + ks * 32 + b_kb);
                uint32_t offL = sw128((b_n + p * 16) * 128 + 64 + ks * 32 + b_kb);
                ldsm_x4(bh[0], bh[1], bh[2], bh[3], tBu + offH);
                ldsm_x4(bl[0], bl[1], bl[2], bl[3], tBu + offL);
#pragma unroll
                for (int mb = 0; mb < 2; mb++) {
#pragma unroll
                    for (int half = 0; half < 2; half++) {
                        float* d = acc[mb][p * 2 + half];
                        mma_fp16(d, ah[mb], &bh[half * 2]);
                        mma_fp16(d, ah[mb], &bl[half * 2]);
                        mma_fp16(d, al[mb], &bh[half * 2]);
                    }
                }
            }
        }
        __syncthreads();
    }

    float* Cp = Cpart + (size_t)z * MSLOT * N;
#pragma unroll
    for (int mb = 0; mb < 2; mb++) {
        int row0 = bm + wm * 32 + mb * 16 + (lane >> 2);
#pragma unroll
        for (int nb = 0; nb < 8; nb++) {
            int col = bn + wn * 64 + nb * 8 + (lane & 3) * 2;
            *(float2*)&Cp[(size_t)row0 * N + col] = make_float2(acc[mb][nb][0], acc[mb][nb][1]);
            *(float2*)&Cp[(size_t)(row0 + 8) * N + col] = make_float2(acc[mb][nb][2], acc[mb][nb][3]);
        }
    }
}

// reduce split-K partials
template <bool RELU>
__global__ void reduce_sk(const float* __restrict__ Cpart, const float* __restrict__ bias,
                          float* __restrict__ C, int MN, int N, int SK)
{
    int i = blockIdx.x * 256 + threadIdx.x;
    if (i >= MN) return;
    float s = bias[i % N];
    for (int z = 0; z < SK; z++) s += Cpart[(size_t)z * MN + i];
    if (RELU) s = fmaxf(s, 0.f);
    C[i] = s;
}

// ================= scores GEMM: HMMA fp16 3-term =========================
__global__ __launch_bounds__(256) void scores_gemm_mma(
    const float* __restrict__ A,
    const __half* __restrict__ Bh, const __half* __restrict__ Bl,
    const float* __restrict__ mbias,
    float* __restrict__ out_scores, float* __restrict__ out_gate)
{
    extern __shared__ char smem[];
    const int tid = threadIdx.x;
    const int wid = tid >> 5, lane = tid & 31;
    const int wm = wid & 3, wn = wid >> 2;
    const int bm = blockIdx.y * 128;
    const int bn = blockIdx.x * 128;
    const int h  = blockIdx.z;
    const int k0 = h * HD;
    const int NCH = HD / KCH;   // 4

    uint32_t sbase = smem_u32(smem);
    uint32_t s0 = (sbase + 1023u) & ~1023u;
    char* smc = smem + (s0 - sbase);

    const int lrow  = tid >> 1;
    const int lhalf = tid & 1;
    const uint32_t stoff0  = sw128(lrow * 128 + lhalf * 32);
    const uint32_t stoff1  = sw128(lrow * 128 + lhalf * 32 + 16);
    const uint32_t stoff0L = sw128(lrow * 128 + 64 + lhalf * 32);
    const uint32_t stoff1L = sw128(lrow * 128 + 64 + lhalf * 32 + 16);

    const int g = lane >> 3, r = lane & 7;
    const int a_m  = wm * 32 + (g & 1) * 8 + r;
    const int a_kb = (g >> 1) * 16;
    const int b_n  = wn * 64 + ((g >> 1) & 1) * 8 + r;
    const int b_kb = (g & 1) * 16;

    float acc[2][8][4];
#pragma unroll
    for (int mb = 0; mb < 2; mb++)
#pragma unroll
        for (int nb = 0; nb < 8; nb++)
#pragma unroll
            for (int q = 0; q < 4; q++) acc[mb][nb][q] = 0.f;

    float4 av[4];
    float4 bhv[2], blv[2];
    {
        const float* ap = &A[(size_t)(bm + lrow) * CORE + k0 + lhalf * 16];
#pragma unroll
        for (int j = 0; j < 4; j++) av[j] = *(const float4*)(ap + 4 * j);
        const __half* bhp = &Bh[(size_t)(bn + lrow) * CORE + k0 + lhalf * 16];
        const __half* blp = &Bl[(size_t)(bn + lrow) * CORE + k0 + lhalf * 16];
        bhv[0] = *(const float4*)bhp; bhv[1] = *(const float4*)(bhp + 8);
        blv[0] = *(const float4*)blp; blv[1] = *(const float4*)(blp + 8);
    }

    for (int c = 0; c < NCH; c++) {
        const int buf = c & 1;
        char* tA = smc + buf * 2 * OPTILE;
        char* tB = tA + OPTILE;
        {
            __half2 hh[8], ll[8];
#pragma unroll
            for (int j = 0; j < 4; j++) {
                float f0 = av[j].x, f1 = av[j].y, f2 = av[j].z, f3 = av[j].w;
                __half h0 = __float2half_rn(f0), h1 = __float2half_rn(f1);
                __half h2 = __float2half_rn(f2), h3 = __float2half_rn(f3);
                hh[2 * j].x = h0; hh[2 * j].y = h1; hh[2 * j + 1].x = h2; hh[2 * j + 1].y = h3;
                ll[2 * j].x = __float2half_rn(f0 - __half2float(h0));
                ll[2 * j].y = __float2half_rn(f1 - __half2float(h1));
                ll[2 * j + 1].x = __float2half_rn(f2 - __half2float(h2));
                ll[2 * j + 1].y = __float2half_rn(f3 - __half2float(h3));
            }
            *(uint4*)(tA + stoff0)  = *(uint4*)&hh[0];
            *(uint4*)(tA + stoff1)  = *(uint4*)&hh[4];
            *(uint4*)(tA + stoff0L) = *(uint4*)&ll[0];
            *(uint4*)(tA + stoff1L) = *(uint4*)&ll[4];
            *(float4*)(tB + stoff0)  = bhv[0];
            *(float4*)(tB + stoff1)  = bhv[1];
            *(float4*)(tB + stoff0L) = blv[0];
            *(float4*)(tB + stoff1L) = blv[1];
        }
        __syncthreads();

        if (c + 1 < NCH) {
            const int kc = k0 + (c + 1) * KCH;
            const float* ap = &A[(size_t)(bm + lrow) * CORE + kc + lhalf * 16];
#pragma unroll
            for (int j = 0; j < 4; j++) av[j] = *(const float4*)(ap + 4 * j);
            const __half* bhp = &Bh[(size_t)(bn + lrow) * CORE + kc + lhalf * 16];
            const __half* blp = &Bl[(size_t)(bn + lrow) * CORE + kc + lhalf * 16];
            bhv[0] = *(const float4*)bhp; bhv[1] = *(const float4*)(bhp + 8);
            blv[0] = *(const float4*)blp; blv[1] = *(const float4*)(blp + 8);
        }

        const uint32_t tAu = s0 + buf * 2 * OPTILE;
        const uint32_t tBu = tAu + OPTILE;
#pragma unroll
        for (int ks = 0; ks < 2; ks++) {
            uint32_t ah[2][4], al[2][4];
#pragma unroll
            for (int mb = 0; mb < 2; mb++) {
                uint32_t offH = sw128((a_m + mb * 16) * 128 + ks * 32 + a_kb);
                uint32_t offL = sw128((a_m + mb * 16) * 128 + 64 + ks * 32 + a_kb);
                ldsm_x4(ah[mb][0], ah[mb][1], ah[mb][2], ah[mb][3], tAu + offH);
                ldsm_x4(al[mb][0], al[mb][1], al[mb][2], al[mb][3], tAu + offL);
            }
#pragma unroll
            for (int p = 0; p < 4; p++) {
                uint32_t bh[4], bl[4];
                uint32_t offH = sw128((b_n + p * 16) * 128 + ks * 32 + b_kb);
                uint32_t offL = sw128((b_n + p * 16) * 128 + 64 + ks * 32 + b_kb);
                ldsm_x4(bh[0], bh[1], bh[2], bh[3], tBu + offH);
                ldsm_x4(bl[0], bl[1], bl[2], bl[3], tBu + offL);
#pragma unroll
                for (int mb = 0; mb < 2; mb++) {
#pragma unroll
                    for (int half = 0; half < 2; half++) {
                        float* d = acc[mb][p * 2 + half];
                        mma_fp16(d, ah[mb], &bh[half * 2]);
                        mma_fp16(d, ah[mb], &bl[half * 2]);
                        mma_fp16(d, al[mb], &bh[half * 2]);
                    }
                }
            }
        }
        __syncthreads();
    }

    const float scale = 0.08838834764831845f;
#pragma unroll
    for (int mb = 0; mb < 2; mb++) {
        int m0 = bm + wm * 32 + mb * 16 + (lane >> 2);
        float bia0 = mbias[h * MSLOT + m0] * 5.0f;
        float bia1 = mbias[h * MSLOT + m0 + 8] * 5.0f;
        size_t base0 = ((size_t)(h * MSLOT + m0)) * NTOK + bn;
        size_t base1 = base0 + (size_t)8 * NTOK;
#pragma unroll
        for (int nb = 0; nb < 8; nb++) {
            int t = wn * 64 + nb * 8 + (lane & 3) * 2;
            float2 v0 = make_float2(acc[mb][nb][0] * scale + bia0, acc[mb][nb][1] * scale + bia0);
            float2 v1 = make_float2(acc[mb][nb][2] * scale + bia1, acc[mb][nb][3] * scale + bia1);
            *(float2*)&out_scores[base0 + t] = v0;
            *(float2*)&out_gate  [base0 + t] = v0;
            *(float2*)&out_scores[base1 + t] = v1;
            *(float2*)&out_gate  [base1 + t] = v1;
        }
    }
}

// ================= top-k over slots ===============
#define TCHUNK 64
__global__ __launch_bounds__(256) void topk_kernel(
    const float* __restrict__ scores,
    unsigned int* __restrict__ idx_out, int* __restrict__ counts)
{
    extern __shared__ float smemf[];
    float* sc_s = smemf;                 // [256][65]
    int*   hist = (int*)(sc_s + 256 * 65);

    const int h  = blockIdx.y;
    const int n0 = blockIdx.x * TCHUNK;
    const int tid = threadIdx.x;
    hist[tid] = 0;

    const int t = tid & 63, mo = tid >> 6;
    for (int rr = 0; rr < 64; rr++) {
        int m = rr * 4 + mo;
        sc_s[m * 65 + t] = scores[((size_t)(h * MSLOT + m)) * NTOK + n0 + t];
    }
    __syncthreads();

    const int warp = tid >> 5, lane = tid & 31;
    for (int tt = warp; tt < TCHUNK; tt += 8) {
        unsigned sel_pack = 0;
#pragma unroll
        for (int rr = 0; rr < TOPK; rr++) {
            float bv = -3.402823466e38f; int bi = 0;
#pragma unroll
            for (int j = 0; j < 8; j++) {
                int m = lane + j * 32;
                float v = sc_s[m * 65 + tt];
                if (v > bv) { bv = v; bi = m; }
            }
#pragma unroll
            for (int off = 16; off; off >>= 1) {
                float ov = __shfl_xor_sync(0xffffffffu, bv, off);
                int   oi = __shfl_xor_sync(0xffffffffu, bi, off);
                if (ov > bv || (ov == bv && oi < bi)) { bv = ov; bi = oi; }
            }
            if (lane == 0) sc_s[bi * 65 + tt] = -3.402823466e38f;
            __syncwarp();
            sel_pack |= ((unsigned)bi) << (8 * rr);
        }
        if (lane == 0) {
            idx_out[h * NTOK + n0 + tt] = sel_pack;
            atomicAdd(&hist[sel_pack & 255], 1);
            atomicAdd(&hist[(sel_pack >> 8) & 255], 1);
            atomicAdd(&hist[(sel_pack >> 16) & 255], 1);
            atomicAdd(&hist[(sel_pack >> 24) & 255], 1);
        }
    }
    __syncthreads();
    if (hist[tid]) atomicAdd(&counts[h * MSLOT + tid], hist[tid]);
}

// ---------------- attended accumulation (reads kvh+kvl) ----------------
__global__ __launch_bounds__(256) void attend_accum(
    const __half* __restrict__ kvh, const __half* __restrict__ kvl,
    const unsigned int* __restrict__ idx, float* __restrict__ att)
{
    extern __shared__ float a_s[];
    const int h  = blockIdx.y;
    const int n0 = blockIdx.x * 1024;
    const int tid = threadIdx.x;
    for (int i = tid; i < MSLOT * HD; i += 256) a_s[i] = 0.f;
    __syncthreads();

    const int warp = tid >> 5, lane = tid & 31;
    const int mlo = warp * 32, mhi = mlo + 32;

    for (int t = 0; t < 1024; t++) {
        unsigned p = idx[h * NTOK + n0 + t];
        const __half2* hrow = (const __half2*)&kvh[(size_t)(n0 + t) * CORE + h * HD];
        const __half2* lrow = (const __half2*)&kvl[(size_t)(n0 + t) * CORE + h * HD];
#pragma unroll
        for (int r = 0; r < TOPK; r++) {
            int m = (p >> (8 * r)) & 255;
            if (m >= mlo && m < mhi) {
                __half2 h0 = hrow[lane * 2],     h1 = hrow[lane * 2 + 1];
                __half2 l0 = lrow[lane * 2],     l1 = lrow[lane * 2 + 1];
                float4* dst = (float4*)&a_s[m * HD + lane * 4];
                float4 d = *dst;
                d.x += __half2float(h0.x) + __half2float(l0.x);
                d.y += __half2float(h0.y) + __half2float(l0.y);
                d.z += __half2float(h1.x) + __half2float(l1.x);
                d.w += __half2float(h1.y) + __half2float(l1.y);
                *dst = d;
            }
        }
    }
    __syncthreads();
    for (int i = tid; i < MSLOT * HD; i += 256) {
        float v = a_s[i];
        if (v != 0.f) atomicAdd(&att[(size_t)h * MSLOT * HD + i], v);
    }
}

// ---------------- build upd_in ----------------
__global__ void build_updin(const float* __restrict__ mem,
                            const float* __restrict__ att,
                            float* __restrict__ out)
{
    int row = blockIdx.x, tid = threadIdx.x;
    for (int i = tid; i < 2 * CORE; i += 256) {
        float v;
        if (i < CORE) v = mem[(size_t)row * CORE + i];
        else {
            int c = i - CORE; int h = c >> 7, d = c & 127;
            v = att[(h << 15) + row * HD + d];
        }
        out[(size_t)row * 2 * CORE + i] = v;
    }
}

// ---------------- layernorm ----------------
__global__ void ln_kernel(const float* __restrict__ x, const float* __restrict__ g,
                          const float* __restrict__ b, float* __restrict__ y, int L)
{
    int row = blockIdx.x, tid = threadIdx.x;
    const float* xr = &x[(size_t)row * L];
    float s = 0.f, s2 = 0.f;
    for (int i = tid; i < L; i += 256) { float v = xr[i]; s += v; s2 += v * v; }
    __shared__ float rs[8], rs2[8];
#pragma unroll
    for (int o = 16; o; o >>= 1) {
        s  += __shfl_xor_sync(0xffffffffu, s, o);
        s2 += __shfl_xor_sync(0xffffffffu, s2, o);
    }
    if ((tid & 31) == 0) { rs[tid >> 5] = s; rs2[tid >> 5] = s2; }
    __syncthreads();
    if (tid < 32) {
        s  = (tid < 8) ? rs[tid]  : 0.f;
        s2 = (tid < 8) ? rs2[tid] : 0.f;
#pragma unroll
        for (int o = 4; o; o >>= 1) {
            s  += __shfl_xor_sync(0xffffffffu, s, o);
            s2 += __shfl_xor_sync(0xffffffffu, s2, o);
        }
        if (tid == 0) { rs[0] = s; rs2[0] = s2; }
    }
    __syncthreads();
    float mu = rs[0] / (float)L;
    float var = rs2[0] / (float)L - mu * mu;
    float r = rsqrtf(var + 1e-5f);
    for (int i = tid; i < L; i += 256)
        y[(size_t)row * L + i] = (xr[i] - mu) * r * g[i] + b[i];
}

// ---------------- load fraction ----------------
__global__ void lf_kernel(const int* __restrict__ counts, float* __restrict__ out)
{
    int m = threadIdx.x;
    int s = 0;
#pragma unroll
    for (int h = 0; h < NH; h++) s += counts[h * MSLOT + m];
    out[m] = (float)s * 0.125f;
}

// ---------------- host launcher (two-stream overlap) ----------------
extern "C" void kernel_launch(void* const* d_in, const int* in_sizes, int n_in,
                              void* d_out, int out_size)
{
    const float* bq_in   = (const float*)d_in[0];
    const float* mem     = (const float*)d_in[1];
    const float* Wq      = (const float*)d_in[2];
    const float* bq      = (const float*)d_in[3];
    const float* Ws1     = (const float*)d_in[4];
    const float* bs1     = (const float*)d_in[5];
    const float* Ws2     = (const float*)d_in[6];
    const float* bs2     = (const float*)d_in[7];
    const float* mbias   = (const float*)d_in[8];
    const float* ln1_g   = (const float*)d_in[9];
    const float* ln1_b   = (const float*)d_in[10];
    const float* Wu1     = (const float*)d_in[11];
    const float* bu1     = (const float*)d_in[12];
    const float* Wu2     = (const float*)d_in[13];
    const float* bu2     = (const float*)d_in[14];
    const float* lno_g   = (const float*)d_in[15];
    const float* lno_b   = (const float*)d_in[16];

    float* out = (float*)d_out;
    float* out_dyn    = out;
    float* out_scores = out + (size_t)MSLOT * CORE;
    float* out_gate   = out_scores + (size_t)NH * MSLOT * NTOK;
    float* out_lf     = out_gate + (size_t)NH * MSLOT * NTOK;

    void *p;
    cudaGetSymbolAddress(&p, g_kvh);     __half* kvh = (__half*)p;
    cudaGetSymbolAddress(&p, g_kvl);     __half* kvl = (__half*)p;
    cudaGetSymbolAddress(&p, g_hid);     float* hid = (float*)p;
    cudaGetSymbolAddress(&p, g_qslots);  float* qs  = (float*)p;
    cudaGetSymbolAddress(&p, g_att);     float* att = (float*)p;
    cudaGetSymbolAddress(&p, g_idx);     unsigned int* idxb = (unsigned int*)p;
    cudaGetSymbolAddress(&p, g_counts);  int* cnt = (int*)p;
    cudaGetSymbolAddress(&p, g_updin);   float* ui = (float*)p;
    cudaGetSymbolAddress(&p, g_h1);      float* h1 = (float*)p;
    cudaGetSymbolAddress(&p, g_hu);      float* hu = (float*)p;
    cudaGetSymbolAddress(&p, g_h2);      float* h2 = (float*)p;
    cudaGetSymbolAddress(&p, g_part);    float* part = (float*)p;
    cudaGetSymbolAddress(&p, g_BhiT);    __half* BhiT = (__half*)p;
    cudaGetSymbolAddress(&p, g_BloT);    __half* BloT = (__half*)p;
    cudaGetSymbolAddress(&p, g_W1h);     __half* W1h = (__half*)p;
    cudaGetSymbolAddress(&p, g_W1l);     __half* W1l = (__half*)p;
    cudaGetSymbolAddress(&p, g_W2h);     __half* W2h = (__half*)p;
    cudaGetSymbolAddress(&p, g_W2l);     __half* W2l = (__half*)p;
    cudaGetSymbolAddress(&p, g_U1h);     __half* U1h = (__half*)p;
    cudaGetSymbolAddress(&p, g_U1l);     __half* U1l = (__half*)p;
    cudaGetSymbolAddress(&p, g_U2h);     __half* U2h = (__half*)p;
    cudaGetSymbolAddress(&p, g_U2l);     __half* U2l = (__half*)p;

    int smkv = 6 * OPTILE + 1024;
    cudaFuncSetAttribute(kv_gemm_mma, cudaFuncAttributeMaxDynamicSharedMemorySize, smkv);
    int smg = 4 * OPTILE + 1024;
    cudaFuncSetAttribute(gemm_sk_mma, cudaFuncAttributeMaxDynamicSharedMemorySize, smg);
    cudaFuncSetAttribute(scores_gemm_mma, cudaFuncAttributeMaxDynamicSharedMemorySize, smg);
    int smt = 256 * 65 * 4 + 1024;
    cudaFuncSetAttribute(topk_kernel, cudaFuncAttributeMaxDynamicSharedMemorySize, smt);
    int sm3 = MSLOT * HD * 4;
    cudaFuncSetAttribute(attend_accum, cudaFuncAttributeMaxDynamicSharedMemorySize, sm3);

    // side stream + events (host-side objects; created fresh, capture-safe)
    cudaStream_t s1;
    cudaStreamCreateWithFlags(&s1, cudaStreamNonBlocking);
    cudaEvent_t eFork, eQs, eU;
    cudaEventCreateWithFlags(&eFork, cudaEventDisableTiming);
    cudaEventCreateWithFlags(&eQs,   cudaEventDisableTiming);
    cudaEventCreateWithFlags(&eU,    cudaEventDisableTiming);

    // fork side stream from main stream
    cudaEventRecord(eFork, 0);
    cudaStreamWaitEvent(s1, eFork, 0);

    // main stream: launches #1-#5 then kv at #6 (ncu -s 5 -c 1 target)
    cudaMemsetAsync(cnt, 0, NH * MSLOT * sizeof(int));                               // 1
    cudaMemsetAsync(att, 0, NH * MSLOT * HD * sizeof(float));                        // 2
    transB_gen<<<dim3(CORE / 32, DM / 32), dim3(32, 8)>>>(Wq, BhiT, BloT, DM, CORE); // 3
    // side stream: independent weight transposes (issued as #4, #5)
    transB_gen<<<dim3(INTER / 32, CORE / 32), dim3(32, 8), 0, s1>>>(Ws1, W1h, W1l, CORE, INTER); // 4
    transB_gen<<<dim3(CORE / 32, INTER / 32), dim3(32, 8), 0, s1>>>(Ws2, W2h, W2l, INTER, CORE); // 5
    // 6: kv GEMM (main)
    kv_gemm_mma<<<dim3(CORE / 128, NTOK / 128), 256, smkv>>>(bq_in, BhiT, BloT, bq, kvh, kvl);

    // side stream: q_slots MLP (overlaps kv), then U transposes
    gemm_sk_mma<<<dim3(INTER / 128, 2, 4), 256, smg, s1>>>(mem, W1h, W1l, part, CORE, 256, INTER);
    reduce_sk<true><<<(MSLOT * INTER + 255) / 256, 256, 0, s1>>>(part, bs1, hid, MSLOT * INTER, INTER, 4);
    gemm_sk_mma<<<dim3(CORE / 128, 2, 16), 256, smg, s1>>>(hid, W2h, W2l, part, INTER, 256, CORE);
    reduce_sk<false><<<(MSLOT * CORE + 255) / 256, 256, 0, s1>>>(part, bs2, qs, MSLOT * CORE, CORE, 16);
    cudaEventRecord(eQs, s1);
    transB_gen<<<dim3(2 * CORE / 32, 2 * CORE / 32), dim3(32, 8), 0, s1>>>(Wu1, U1h, U1l, 2 * CORE, 2 * CORE);
    transB_gen<<<dim3(CORE / 32, 2 * CORE / 32), dim3(32, 8), 0, s1>>>(Wu2, U2h, U2l, 2 * CORE, CORE);
    cudaEventRecord(eU, s1);

    // join: scores needs kv (main) + qslots (s1)
    cudaStreamWaitEvent(0, eQs, 0);
    scores_gemm_mma<<<dim3(NTOK / 128, MSLOT / 128, NH), 256, smg>>>(
        qs, kvh, kvl, mbias, out_scores, out_gate);
    topk_kernel<<<dim3(NTOK / TCHUNK, NH), 256, smt>>>(out_scores, idxb, cnt);

    attend_accum<<<dim3(NTOK / 1024, NH), 256, sm3>>>(kvh, kvl, idxb, att);

    build_updin<<<MSLOT, 256>>>(mem, att, ui);
    ln_kernel<<<MSLOT, 256>>>(ui, ln1_g, ln1_b, h1, 2 * CORE);

    // join: update MLP needs U transposes (s1) — also orders g_part reuse
    cudaStreamWaitEvent(0, eU, 0);
    gemm_sk_mma<<<dim3(2 * CORE / 128, 2, 8), 256, smg>>>(h1, U1h, U1l, part, 2 * CORE, 256, 2 * CORE);
    reduce_sk<true><<<(MSLOT * 2 * CORE + 255) / 256, 256>>>(part, bu1, hu, MSLOT * 2 * CORE, 2 * CORE, 8);
    gemm_sk_mma<<<dim3(CORE / 128, 2, 8), 256, smg>>>(hu, U2h, U2l, part, 2 * CORE, 256, CORE);
    reduce_sk<false><<<(MSLOT * CORE + 255) / 256, 256>>>(part, bu2, h2, MSLOT * CORE, CORE, 8);
    ln_kernel<<<MSLOT, 256>>>(h2, lno_g, lno_b, out_dyn, CORE);

    lf_kernel<<<1, MSLOT>>>(cnt, out_lf);

    // release host-side handles (events/stream objects; no device memory)
    cudaEventDestroy(eFork);
    cudaEventDestroy(eQs);
    cudaEventDestroy(eU);
    cudaStreamDestroy(s1);
}